// round 2
// baseline (speedup 1.0000x reference)
#include <cuda_runtime.h>

#define HEADS 16
#define DH    64
#define NB    2
#define T1    2048
#define T2    2048
#define HID   1024

#define LDS_  65
#define SM_BYTES (3 * 64 * LDS_ * 4)

// scratch: attention context in [N, T1, HID] layout (heads interleaved back)
__device__ float g_ctx[(size_t)NB * T1 * HID];
__device__ int   g_mask_flag;

__global__ void zero_flag_k() { g_mask_flag = 0; }

__global__ void scan_mask_k(const float* __restrict__ m, int n4) {
    int i = blockIdx.x * blockDim.x + threadIdx.x;
    bool nz = false;
    for (int idx = i; idx < n4; idx += gridDim.x * blockDim.x) {
        float4 v = ((const float4*)m)[idx];
        nz |= (v.x != 0.f) || (v.y != 0.f) || (v.z != 0.f) || (v.w != 0.f);
    }
    if (nz) atomicOr(&g_mask_flag, 1);
}

// Flash attention, fp32. Block = 64 q-rows x one (b,h). 256 threads, 4x4 micro-tile.
__global__ __launch_bounds__(256) void attn_k(
    const float* __restrict__ q, const float* __restrict__ k,
    const float* __restrict__ v, const float* __restrict__ mask)
{
    extern __shared__ float sm[];
    float* Qs  = sm;                 // [64][65]  Q tile (rows=q, cols=d)
    float* KPs = sm + 64 * LDS_;     // [64][65]  K tile (rows=kseq, cols=d), reused for P (rows=q, cols=kseq)
    float* Vs  = sm + 2 * 64 * LDS_; // [64][65]  V tile (rows=kseq, cols=d)

    const int tid = threadIdx.x;
    const int tx = tid & 15, ty = tid >> 4;          // 16x16 thread grid
    const int lr = tid >> 2, lc = (tid & 3) * 16;    // tile-load mapping

    const int bh = blockIdx.y;
    const int b = bh >> 4, h = bh & 15;
    const int q0 = blockIdx.x * 64;

    const float* qb = q + ((size_t)b * T1) * HID + h * DH;
    const float* kb = k + ((size_t)b * T2) * HID + h * DH;
    const float* vb = v + ((size_t)b * T2) * HID + h * DH;
    const float* mb = mask + (size_t)b * T2 * T2;

    const bool use_mask = (g_mask_flag != 0);

    // load Q tile once
    {
        const float* src = qb + (size_t)(q0 + lr) * HID + lc;
        float* dst = Qs + lr * LDS_ + lc;
        #pragma unroll
        for (int m4 = 0; m4 < 4; m4++) {
            float4 t = ((const float4*)src)[m4];
            dst[4 * m4 + 0] = t.x; dst[4 * m4 + 1] = t.y;
            dst[4 * m4 + 2] = t.z; dst[4 * m4 + 3] = t.w;
        }
    }

    float o[4][4];
    float mrow[4], lrow[4];
    #pragma unroll
    for (int i = 0; i < 4; i++) {
        mrow[i] = -1e30f; lrow[i] = 0.f;
        #pragma unroll
        for (int j = 0; j < 4; j++) o[i][j] = 0.f;
    }

    for (int k0 = 0; k0 < T2; k0 += 64) {
        // load K, V tiles
        {
            const float* srck = kb + (size_t)(k0 + lr) * HID + lc;
            const float* srcv = vb + (size_t)(k0 + lr) * HID + lc;
            float* dk = KPs + lr * LDS_ + lc;
            float* dv = Vs + lr * LDS_ + lc;
            #pragma unroll
            for (int m4 = 0; m4 < 4; m4++) {
                float4 t = ((const float4*)srck)[m4];
                dk[4 * m4 + 0] = t.x; dk[4 * m4 + 1] = t.y;
                dk[4 * m4 + 2] = t.z; dk[4 * m4 + 3] = t.w;
                float4 u = ((const float4*)srcv)[m4];
                dv[4 * m4 + 0] = u.x; dv[4 * m4 + 1] = u.y;
                dv[4 * m4 + 2] = u.z; dv[4 * m4 + 3] = u.w;
            }
        }
        __syncthreads();

        // S = Q Kᵀ  (rows 4*ty+i, cols 4*tx+j)
        float s[4][4];
        #pragma unroll
        for (int i = 0; i < 4; i++)
            #pragma unroll
            for (int j = 0; j < 4; j++) s[i][j] = 0.f;

        #pragma unroll 8
        for (int kk = 0; kk < 64; kk++) {
            float a0 = Qs[(4 * ty + 0) * LDS_ + kk];
            float a1 = Qs[(4 * ty + 1) * LDS_ + kk];
            float a2 = Qs[(4 * ty + 2) * LDS_ + kk];
            float a3 = Qs[(4 * ty + 3) * LDS_ + kk];
            float b0 = KPs[(4 * tx + 0) * LDS_ + kk];
            float b1 = KPs[(4 * tx + 1) * LDS_ + kk];
            float b2 = KPs[(4 * tx + 2) * LDS_ + kk];
            float b3 = KPs[(4 * tx + 3) * LDS_ + kk];
            s[0][0] += a0 * b0; s[0][1] += a0 * b1; s[0][2] += a0 * b2; s[0][3] += a0 * b3;
            s[1][0] += a1 * b0; s[1][1] += a1 * b1; s[1][2] += a1 * b2; s[1][3] += a1 * b3;
            s[2][0] += a2 * b0; s[2][1] += a2 * b1; s[2][2] += a2 * b2; s[2][3] += a2 * b3;
            s[3][0] += a3 * b0; s[3][1] += a3 * b1; s[3][2] += a3 * b2; s[3][3] += a3 * b3;
        }

        if (use_mask) {
            #pragma unroll
            for (int i = 0; i < 4; i++) {
                float4 mv = *(const float4*)(mb + (size_t)(q0 + 4 * ty + i) * T2 + k0 + 4 * tx);
                s[i][0] += mv.x; s[i][1] += mv.y; s[i][2] += mv.z; s[i][3] += mv.w;
            }
        }

        // online softmax: row max over the 16 tx-threads of this half-warp group
        float corr[4];
        #pragma unroll
        for (int i = 0; i < 4; i++) {
            float mt = fmaxf(fmaxf(s[i][0], s[i][1]), fmaxf(s[i][2], s[i][3]));
            #pragma unroll
            for (int off = 1; off < 16; off <<= 1)
                mt = fmaxf(mt, __shfl_xor_sync(0xffffffffu, mt, off));
            float mn = fmaxf(mrow[i], mt);
            corr[i] = __expf(mrow[i] - mn);
            mrow[i] = mn;
        }

        __syncthreads();  // all K reads done before P overwrites the buffer

        float padd[4];
        #pragma unroll
        for (int i = 0; i < 4; i++) {
            float p0 = __expf(s[i][0] - mrow[i]);
            float p1 = __expf(s[i][1] - mrow[i]);
            float p2 = __expf(s[i][2] - mrow[i]);
            float p3 = __expf(s[i][3] - mrow[i]);
            float* pr = KPs + (4 * ty + i) * LDS_ + 4 * tx;
            pr[0] = p0; pr[1] = p1; pr[2] = p2; pr[3] = p3;
            float ps = p0 + p1 + p2 + p3;
            #pragma unroll
            for (int off = 1; off < 16; off <<= 1)
                ps += __shfl_xor_sync(0xffffffffu, ps, off);
            padd[i] = ps;
        }
        #pragma unroll
        for (int i = 0; i < 4; i++) {
            lrow[i] = lrow[i] * corr[i] + padd[i];
            #pragma unroll
            for (int j = 0; j < 4; j++) o[i][j] *= corr[i];
        }
        __syncthreads();  // P visible to all

        // O += P V   (rows 4*ty+i = q, cols 4*tx+j = d)
        #pragma unroll 8
        for (int kk = 0; kk < 64; kk++) {
            float a0 = KPs[(4 * ty + 0) * LDS_ + kk];
            float a1 = KPs[(4 * ty + 1) * LDS_ + kk];
            float a2 = KPs[(4 * ty + 2) * LDS_ + kk];
            float a3 = KPs[(4 * ty + 3) * LDS_ + kk];
            float b0 = Vs[kk * LDS_ + 4 * tx + 0];
            float b1 = Vs[kk * LDS_ + 4 * tx + 1];
            float b2 = Vs[kk * LDS_ + 4 * tx + 2];
            float b3 = Vs[kk * LDS_ + 4 * tx + 3];
            o[0][0] += a0 * b0; o[0][1] += a0 * b1; o[0][2] += a0 * b2; o[0][3] += a0 * b3;
            o[1][0] += a1 * b0; o[1][1] += a1 * b1; o[1][2] += a1 * b2; o[1][3] += a1 * b3;
            o[2][0] += a2 * b0; o[2][1] += a2 * b1; o[2][2] += a2 * b2; o[2][3] += a2 * b3;
            o[3][0] += a3 * b0; o[3][1] += a3 * b1; o[3][2] += a3 * b2; o[3][3] += a3 * b3;
        }
        __syncthreads();  // before next tile overwrites K/P and V
    }

    // normalize + write ctx in [N, T1, HID] layout
    #pragma unroll
    for (int i = 0; i < 4; i++) {
        float inv = 1.0f / lrow[i];
        float4 t = make_float4(o[i][0] * inv, o[i][1] * inv, o[i][2] * inv, o[i][3] * inv);
        *(float4*)(g_ctx + (size_t)(b * T1 + q0 + 4 * ty + i) * HID + h * DH + 4 * tx) = t;
    }
}

// out = relu(ctx @ Wᵀ + b), 64x64 tiles
__global__ __launch_bounds__(256) void proj_k(
    const float* __restrict__ w, const float* __restrict__ bias,
    float* __restrict__ out)
{
    __shared__ float As[64 * LDS_];
    __shared__ float Bs[64 * LDS_];
    const int tid = threadIdx.x;
    const int tx = tid & 15, ty = tid >> 4;
    const int lr = tid >> 2, lc = (tid & 3) * 16;
    const int r0 = blockIdx.x * 64, n0 = blockIdx.y * 64;

    float acc[4][4];
    #pragma unroll
    for (int i = 0; i < 4; i++)
        #pragma unroll
        for (int j = 0; j < 4; j++) acc[i][j] = 0.f;

    for (int e0 = 0; e0 < HID; e0 += 64) {
        const float* sa = g_ctx + (size_t)(r0 + lr) * HID + e0 + lc;
        const float* sb = w + (size_t)(n0 + lr) * HID + e0 + lc;
        float* da = As + lr * LDS_ + lc;
        float* db = Bs + lr * LDS_ + lc;
        #pragma unroll
        for (int m4 = 0; m4 < 4; m4++) {
            float4 t = ((const float4*)sa)[m4];
            da[4 * m4 + 0] = t.x; da[4 * m4 + 1] = t.y;
            da[4 * m4 + 2] = t.z; da[4 * m4 + 3] = t.w;
            float4 u = ((const float4*)sb)[m4];
            db[4 * m4 + 0] = u.x; db[4 * m4 + 1] = u.y;
            db[4 * m4 + 2] = u.z; db[4 * m4 + 3] = u.w;
        }
        __syncthreads();

        #pragma unroll 8
        for (int kk = 0; kk < 64; kk++) {
            float a0 = As[(4 * ty + 0) * LDS_ + kk];
            float a1 = As[(4 * ty + 1) * LDS_ + kk];
            float a2 = As[(4 * ty + 2) * LDS_ + kk];
            float a3 = As[(4 * ty + 3) * LDS_ + kk];
            float b0 = Bs[(4 * tx + 0) * LDS_ + kk];
            float b1 = Bs[(4 * tx + 1) * LDS_ + kk];
            float b2 = Bs[(4 * tx + 2) * LDS_ + kk];
            float b3 = Bs[(4 * tx + 3) * LDS_ + kk];
            acc[0][0] += a0 * b0; acc[0][1] += a0 * b1; acc[0][2] += a0 * b2; acc[0][3] += a0 * b3;
            acc[1][0] += a1 * b0; acc[1][1] += a1 * b1; acc[1][2] += a1 * b2; acc[1][3] += a1 * b3;
            acc[2][0] += a2 * b0; acc[2][1] += a2 * b1; acc[2][2] += a2 * b2; acc[2][3] += a2 * b3;
            acc[3][0] += a3 * b0; acc[3][1] += a3 * b1; acc[3][2] += a3 * b2; acc[3][3] += a3 * b3;
        }
        __syncthreads();
    }

    float4 bv = *(const float4*)(bias + n0 + 4 * tx);
    #pragma unroll
    for (int i = 0; i < 4; i++) {
        float4 t;
        t.x = fmaxf(acc[i][0] + bv.x, 0.f);
        t.y = fmaxf(acc[i][1] + bv.y, 0.f);
        t.z = fmaxf(acc[i][2] + bv.z, 0.f);
        t.w = fmaxf(acc[i][3] + bv.w, 0.f);
        *(float4*)(out + (size_t)(r0 + 4 * ty + i) * HID + n0 + 4 * tx) = t;
    }
}

extern "C" void kernel_launch(void* const* d_in, const int* in_sizes, int n_in,
                              void* d_out, int out_size)
{
    const float* q    = (const float*)d_in[0];
    const float* ek   = (const float*)d_in[1];
    const float* ev   = (const float*)d_in[2];
    const float* mask = (const float*)d_in[3];
    const float* wo_w = (const float*)d_in[4];
    const float* wo_b = (const float*)d_in[5];
    float* out = (float*)d_out;

    cudaFuncSetAttribute(attn_k, cudaFuncAttributeMaxDynamicSharedMemorySize, SM_BYTES);

    zero_flag_k<<<1, 1>>>();
    scan_mask_k<<<1024, 256>>>(mask, NB * T2 * T2 / 4);

    dim3 gA(T1 / 64, NB * HEADS);
    attn_k<<<gA, 256, SM_BYTES>>>(q, ek, ev, mask);

    dim3 gP(NB * T1 / 64, HID / 64);
    proj_k<<<gP, 256>>>(wo_w, wo_b, out);
}

// round 4
// speedup vs baseline: 3.3949x; 3.3949x over previous
#include <cuda_runtime.h>
#include <cuda_bf16.h>
#include <cstdint>

#define HEADS 16
#define DH    64
#define NB    2
#define T1    2048
#define T2    2048
#define HID   1024
#define BH    (NB*HEADS)

// ---------------- device scratch ----------------
__device__ __nv_bfloat16 g_qhi[(size_t)NB * T1 * HID];
__device__ __nv_bfloat16 g_qlo[(size_t)NB * T1 * HID];
__device__ __nv_bfloat16 g_khi[(size_t)NB * T2 * HID];
__device__ __nv_bfloat16 g_klo[(size_t)NB * T2 * HID];
__device__ __nv_bfloat16 g_vhi[(size_t)NB * T2 * HID];
__device__ __nv_bfloat16 g_vlo[(size_t)NB * T2 * HID];
__device__ __nv_bfloat16 g_whi[(size_t)HID * HID];
__device__ __nv_bfloat16 g_wlo[(size_t)HID * HID];
__device__ __nv_bfloat16 g_chi[(size_t)NB * T1 * HID];
__device__ __nv_bfloat16 g_clo[(size_t)NB * T1 * HID];
__device__ int g_mask_flag;

// ---------------- helpers ----------------
__device__ __forceinline__ uint32_t smem_u32(const void* p) {
    uint32_t a;
    asm("{ .reg .u64 t; cvta.to.shared.u64 t, %1; cvt.u32.u64 %0, t; }" : "=r"(a) : "l"(p));
    return a;
}
__device__ __forceinline__ uint32_t sw128(uint32_t o) { return o ^ ((o >> 3) & 0x70); }

__device__ __forceinline__ float bf16r(float x) { return __bfloat162float(__float2bfloat16(x)); }
__device__ __forceinline__ uint32_t packbf2(float lo, float hi) {
    uint32_t r;
    asm("cvt.rn.bf16x2.f32 %0, %1, %2;" : "=r"(r) : "f"(hi), "f"(lo));
    return r;
}
__device__ __forceinline__ void packsplit(float x, float y, uint32_t& hi, uint32_t& lo) {
    float hx = bf16r(x), hy = bf16r(y);
    hi = packbf2(hx, hy);
    lo = packbf2(x - hx, y - hy);
}

__device__ __forceinline__ void ldsm4(uint32_t& r0, uint32_t& r1, uint32_t& r2, uint32_t& r3, uint32_t a) {
    asm volatile("ldmatrix.sync.aligned.m8n8.x4.shared.b16 {%0,%1,%2,%3}, [%4];"
        : "=r"(r0), "=r"(r1), "=r"(r2), "=r"(r3) : "r"(a));
}
__device__ __forceinline__ void ldsm4t(uint32_t& r0, uint32_t& r1, uint32_t& r2, uint32_t& r3, uint32_t a) {
    asm volatile("ldmatrix.sync.aligned.m8n8.x4.trans.shared.b16 {%0,%1,%2,%3}, [%4];"
        : "=r"(r0), "=r"(r1), "=r"(r2), "=r"(r3) : "r"(a));
}
__device__ __forceinline__ void mmabf(float* c, const uint32_t* a, uint32_t b0, uint32_t b1) {
    asm volatile("mma.sync.aligned.m16n8k16.row.col.f32.bf16.bf16.f32 "
        "{%0,%1,%2,%3}, {%4,%5,%6,%7}, {%8,%9}, {%0,%1,%2,%3};"
        : "+f"(c[0]), "+f"(c[1]), "+f"(c[2]), "+f"(c[3])
        : "r"(a[0]), "r"(a[1]), "r"(a[2]), "r"(a[3]), "r"(b0), "r"(b1));
}

#define CP16(dst, src) asm volatile("cp.async.cg.shared.global [%0], [%1], 16;" :: "r"(dst), "l"(src) : "memory")
#define CP_COMMIT()    asm volatile("cp.async.commit_group;" ::: "memory")
#define CP_WAIT1()     asm volatile("cp.async.wait_group 1;" ::: "memory")
#define CP_WAIT0()     asm volatile("cp.async.wait_group 0;" ::: "memory")

// ---------------- mask scan ----------------
__global__ void zero_flag_k() { g_mask_flag = 0; }
__global__ void scan_mask_k(const float* __restrict__ m, int n4) {
    int i = blockIdx.x * blockDim.x + threadIdx.x;
    bool nz = false;
    for (int idx = i; idx < n4; idx += gridDim.x * blockDim.x) {
        float4 v = ((const float4*)m)[idx];
        nz |= (v.x != 0.f) || (v.y != 0.f) || (v.z != 0.f) || (v.w != 0.f);
    }
    if (nz) atomicOr(&g_mask_flag, 1);
}

// ---------------- prep: fp32 -> bf16 hi/lo ----------------
__global__ __launch_bounds__(256) void split2_k(const float* __restrict__ src,
                                                __nv_bfloat16* __restrict__ hi,
                                                __nv_bfloat16* __restrict__ lo) {
    size_t i = (size_t)blockIdx.x * 256 + threadIdx.x;
    float2 u = ((const float2*)src)[i];
    float h0 = bf16r(u.x), h1 = bf16r(u.y);
    ((uint32_t*)hi)[i] = packbf2(h0, h1);
    ((uint32_t*)lo)[i] = packbf2(u.x - h0, u.y - h1);
}

// ---------------- attention (FA2 on mma.sync bf16x3) ----------------
// smem: two 32KB buffers (KH|KL|VH|VL, 8KB each, 64 rows x 128B, sw128), +1KB align pad
#define AT_BUF   32768
#define AO_KH    0
#define AO_KL    8192
#define AO_VH    16384
#define AO_VL    24576
#define ATT_SMEM (2 * AT_BUF + 1024)

__device__ __forceinline__ void issue_tile(uint32_t sbuf, int k0, int tid,
    const __nv_bfloat16* khg, const __nv_bfloat16* klg,
    const __nv_bfloat16* vhg, const __nv_bfloat16* vlg)
{
    #pragma unroll
    for (int j = 0; j < 2; j++) {
        int i = tid * 2 + j;
        int row = i >> 3, seg = i & 7;
        uint32_t dsw = sw128((uint32_t)(row * 128 + seg * 16));
        size_t roff = (size_t)(k0 + row) * HID + seg * 8;
        CP16(sbuf + AO_KH + dsw, khg + roff);
        CP16(sbuf + AO_KL + dsw, klg + roff);
        CP16(sbuf + AO_VH + dsw, vhg + roff);
        CP16(sbuf + AO_VL + dsw, vlg + roff);
    }
}

__global__ __launch_bounds__(256) void attn_tc(const float* __restrict__ mask)
{
    extern __shared__ char smraw[];
    uint32_t sb0 = smem_u32(smraw);
    uint32_t pad = (1024u - (sb0 & 1023u)) & 1023u;
    char* smp = smraw + pad;
    uint32_t sb = sb0 + pad;

    const int tid = threadIdx.x;
    const int w = tid >> 5, l = tid & 31;
    const int bh = blockIdx.y, b = bh >> 4, h = bh & 15;
    const int q0 = blockIdx.x * 128;

    const __nv_bfloat16* khg = g_khi + (size_t)b * T2 * HID + h * DH;
    const __nv_bfloat16* klg = g_klo + (size_t)b * T2 * HID + h * DH;
    const __nv_bfloat16* vhg = g_vhi + (size_t)b * T2 * HID + h * DH;
    const __nv_bfloat16* vlg = g_vlo + (size_t)b * T2 * HID + h * DH;

    // kick off tile 0 into buf 0
    issue_tile(sb, 0, tid, khg, klg, vhg, vlg);
    CP_COMMIT();

    // ---- load Q fragments (persist in registers), staged through buf1 ----
    uint32_t qh_[4][4], ql_[4][4];
    {
        const __nv_bfloat16* qhg = g_qhi + ((size_t)b * T1 + q0) * HID + h * DH;
        const __nv_bfloat16* qlg = g_qlo + ((size_t)b * T1 + q0) * HID + h * DH;
        const uint32_t qrow = (uint32_t)(16 * w + (l & 15));
        #pragma unroll
        for (int pass = 0; pass < 2; pass++) {
            const __nv_bfloat16* src = pass ? qlg : qhg;
            #pragma unroll
            for (int j = 0; j < 4; j++) {
                int i = tid * 4 + j;
                int row = i >> 3, seg = i & 7;
                *(uint4*)(smp + AT_BUF + sw128((uint32_t)(row * 128 + seg * 16))) =
                    *(const uint4*)(src + (size_t)row * HID + seg * 8);
            }
            __syncthreads();
            #pragma unroll
            for (int st = 0; st < 4; st++) {
                uint32_t a = sb + AT_BUF + sw128(qrow * 128 + (uint32_t)(2 * st + (l >> 4)) * 16);
                if (pass == 0) ldsm4(qh_[st][0], qh_[st][1], qh_[st][2], qh_[st][3], a);
                else           ldsm4(ql_[st][0], ql_[st][1], ql_[st][2], ql_[st][3], a);
            }
            __syncthreads();
        }
    }

    const bool use_mask = (g_mask_flag != 0);
    const float* mr0 = mask + ((size_t)b * T2 + (q0 + 16 * w + (l >> 2))) * T2;
    const float* mr1 = mr0 + (size_t)8 * T2;

    // ldmatrix per-thread address components
    const uint32_t krow = (uint32_t)((l & 7) + ((l & 16) >> 1)); // + 16*g
    const uint32_t kseg = (uint32_t)((l >> 3) & 1);              // + 2*st
    const uint32_t vrow = (uint32_t)((l & 7) + (l & 8));         // + 16*st
    const uint32_t vseg = (uint32_t)(l >> 4);                    // + 2*g

    float o_[8][4];
    #pragma unroll
    for (int i = 0; i < 8; i++)
        #pragma unroll
        for (int j = 0; j < 4; j++) o_[i][j] = 0.f;
    float m0 = -1e30f, m1 = -1e30f, l0 = 0.f, l1 = 0.f;

    for (int kt = 0; kt < 32; kt++) {
        uint32_t cur = sb + (uint32_t)(kt & 1) * AT_BUF;
        if (kt + 1 < 32) {
            issue_tile(sb + (uint32_t)((kt + 1) & 1) * AT_BUF, (kt + 1) * 64, tid, khg, klg, vhg, vlg);
            CP_COMMIT();
            CP_WAIT1();
        } else {
            CP_WAIT0();
        }
        __syncthreads();

        // ---- S = Qhi*Khi + Qhi*Klo + Qlo*Khi ----
        float s_[8][4];
        #pragma unroll
        for (int i = 0; i < 8; i++)
            #pragma unroll
            for (int j = 0; j < 4; j++) s_[i][j] = 0.f;

        #pragma unroll
        for (int st = 0; st < 4; st++) {
            #pragma unroll
            for (int g = 0; g < 4; g++) {
                uint32_t off = sw128((uint32_t)((16 * g + krow) * 128 + (2 * st + kseg) * 16));
                uint32_t b0, b1, b2, b3;
                ldsm4(b0, b1, b2, b3, cur + AO_KH + off);
                mmabf(s_[2 * g], qh_[st], b0, b1);
                mmabf(s_[2 * g + 1], qh_[st], b2, b3);
                mmabf(s_[2 * g], ql_[st], b0, b1);
                mmabf(s_[2 * g + 1], ql_[st], b2, b3);
                uint32_t c0, c1, c2, c3;
                ldsm4(c0, c1, c2, c3, cur + AO_KL + off);
                mmabf(s_[2 * g], qh_[st], c0, c1);
                mmabf(s_[2 * g + 1], qh_[st], c2, c3);
            }
        }

        if (use_mask) {
            int k0 = kt * 64;
            #pragma unroll
            for (int nf = 0; nf < 8; nf++) {
                float2 a = *(const float2*)(mr0 + k0 + 8 * nf + 2 * (l & 3));
                float2 c = *(const float2*)(mr1 + k0 + 8 * nf + 2 * (l & 3));
                s_[nf][0] += a.x; s_[nf][1] += a.y;
                s_[nf][2] += c.x; s_[nf][3] += c.y;
            }
        }

        // ---- online softmax (rows t/4 and t/4+8) ----
        float mt0 = -1e30f, mt1 = -1e30f;
        #pragma unroll
        for (int nf = 0; nf < 8; nf++) {
            mt0 = fmaxf(mt0, fmaxf(s_[nf][0], s_[nf][1]));
            mt1 = fmaxf(mt1, fmaxf(s_[nf][2], s_[nf][3]));
        }
        mt0 = fmaxf(mt0, __shfl_xor_sync(0xffffffffu, mt0, 1));
        mt0 = fmaxf(mt0, __shfl_xor_sync(0xffffffffu, mt0, 2));
        mt1 = fmaxf(mt1, __shfl_xor_sync(0xffffffffu, mt1, 1));
        mt1 = fmaxf(mt1, __shfl_xor_sync(0xffffffffu, mt1, 2));
        float nm0 = fmaxf(m0, mt0), nm1 = fmaxf(m1, mt1);
        float cr0 = __expf(m0 - nm0), cr1 = __expf(m1 - nm1);
        m0 = nm0; m1 = nm1;
        float sum0 = 0.f, sum1 = 0.f;
        #pragma unroll
        for (int nf = 0; nf < 8; nf++) {
            s_[nf][0] = __expf(s_[nf][0] - nm0); sum0 += s_[nf][0];
            s_[nf][1] = __expf(s_[nf][1] - nm0); sum0 += s_[nf][1];
            s_[nf][2] = __expf(s_[nf][2] - nm1); sum1 += s_[nf][2];
            s_[nf][3] = __expf(s_[nf][3] - nm1); sum1 += s_[nf][3];
        }
        sum0 += __shfl_xor_sync(0xffffffffu, sum0, 1);
        sum0 += __shfl_xor_sync(0xffffffffu, sum0, 2);
        sum1 += __shfl_xor_sync(0xffffffffu, sum1, 1);
        sum1 += __shfl_xor_sync(0xffffffffu, sum1, 2);
        l0 = l0 * cr0 + sum0;
        l1 = l1 * cr1 + sum1;
        #pragma unroll
        for (int nf = 0; nf < 8; nf++) {
            o_[nf][0] *= cr0; o_[nf][1] *= cr0;
            o_[nf][2] *= cr1; o_[nf][3] *= cr1;
        }

        // ---- pack P -> A fragments (hi/lo), pure register shuffle ----
        uint32_t ph_[4][4], pl_[4][4];
        #pragma unroll
        for (int st = 0; st < 4; st++) {
            packsplit(s_[2 * st][0],     s_[2 * st][1],     ph_[st][0], pl_[st][0]);
            packsplit(s_[2 * st][2],     s_[2 * st][3],     ph_[st][1], pl_[st][1]);
            packsplit(s_[2 * st + 1][0], s_[2 * st + 1][1], ph_[st][2], pl_[st][2]);
            packsplit(s_[2 * st + 1][2], s_[2 * st + 1][3], ph_[st][3], pl_[st][3]);
        }

        // ---- O += Phi*Vhi + Plo*Vhi + Phi*Vlo ----
        #pragma unroll
        for (int st = 0; st < 4; st++) {
            #pragma unroll
            for (int g = 0; g < 4; g++) {
                uint32_t off = sw128((uint32_t)((16 * st + vrow) * 128 + (2 * g + vseg) * 16));
                uint32_t b0, b1, b2, b3;
                ldsm4t(b0, b1, b2, b3, cur + AO_VH + off);
                mmabf(o_[2 * g], ph_[st], b0, b1);
                mmabf(o_[2 * g + 1], ph_[st], b2, b3);
                mmabf(o_[2 * g], pl_[st], b0, b1);
                mmabf(o_[2 * g + 1], pl_[st], b2, b3);
                uint32_t c0, c1, c2, c3;
                ldsm4t(c0, c1, c2, c3, cur + AO_VL + off);
                mmabf(o_[2 * g], ph_[st], c0, c1);
                mmabf(o_[2 * g + 1], ph_[st], c2, c3);
            }
        }
        __syncthreads();  // buffer reuse barrier
    }

    // ---- epilogue: normalize, split to bf16 hi/lo ctx ----
    float inv0 = 1.0f / l0, inv1 = 1.0f / l1;
    int r0 = q0 + 16 * w + (l >> 2);
    size_t base0 = ((size_t)b * T1 + r0) * HID + h * DH;
    size_t base1 = base0 + (size_t)8 * HID;
    #pragma unroll
    for (int nf = 0; nf < 8; nf++) {
        int col = 8 * nf + 2 * (l & 3);
        uint32_t hi, lo;
        packsplit(o_[nf][0] * inv0, o_[nf][1] * inv0, hi, lo);
        *(uint32_t*)(g_chi + base0 + col) = hi;
        *(uint32_t*)(g_clo + base0 + col) = lo;
        packsplit(o_[nf][2] * inv1, o_[nf][3] * inv1, hi, lo);
        *(uint32_t*)(g_chi + base1 + col) = hi;
        *(uint32_t*)(g_clo + base1 + col) = lo;
    }
}

// ---------------- proj: out = relu(ctx @ W^T + b), mma bf16x3 ----------------
#define PO_AH 0
#define PO_AL 16384
#define PO_BH 32768
#define PO_BL 40960
#define PROJ_SMEM (49152 + 1024)

__global__ __launch_bounds__(256, 2) void proj_tc(const float* __restrict__ bias,
                                                  float* __restrict__ out)
{
    extern __shared__ char smraw[];
    uint32_t sb0 = smem_u32(smraw);
    uint32_t pad = (1024u - (sb0 & 1023u)) & 1023u;
    uint32_t sb = sb0 + pad;

    const int tid = threadIdx.x;
    const int w = tid >> 5, l = tid & 31;
    const int r0c = blockIdx.x * 128, n0 = blockIdx.y * 64;

    const uint32_t arow = (uint32_t)(16 * w + (l & 15));
    const uint32_t aseg = (uint32_t)(l >> 4);
    const uint32_t krow = (uint32_t)((l & 7) + ((l & 16) >> 1));
    const uint32_t kseg = (uint32_t)((l >> 3) & 1);

    float acc[8][4];
    #pragma unroll
    for (int i = 0; i < 8; i++)
        #pragma unroll
        for (int j = 0; j < 4; j++) acc[i][j] = 0.f;

    for (int e0 = 0; e0 < HID; e0 += 64) {
        // load A (ctx hi/lo, 128x64) and B (W hi/lo, 64x64)
        #pragma unroll
        for (int j = 0; j < 4; j++) {
            int i = tid * 4 + j;
            int row = i >> 3, seg = i & 7;
            uint32_t dsw = sw128((uint32_t)(row * 128 + seg * 16));
            size_t roff = (size_t)(r0c + row) * HID + e0 + seg * 8;
            CP16(sb + PO_AH + dsw, g_chi + roff);
            CP16(sb + PO_AL + dsw, g_clo + roff);
        }
        #pragma unroll
        for (int j = 0; j < 2; j++) {
            int i = tid * 2 + j;
            int row = i >> 3, seg = i & 7;
            uint32_t dsw = sw128((uint32_t)(row * 128 + seg * 16));
            size_t roff = (size_t)(n0 + row) * HID + e0 + seg * 8;
            CP16(sb + PO_BH + dsw, g_whi + roff);
            CP16(sb + PO_BL + dsw, g_wlo + roff);
        }
        CP_COMMIT();
        CP_WAIT0();
        __syncthreads();

        uint32_t ah_[4][4], al_[4][4];
        #pragma unroll
        for (int st = 0; st < 4; st++) {
            uint32_t a = sb + sw128(arow * 128 + (uint32_t)(2 * st + aseg) * 16);
            ldsm4(ah_[st][0], ah_[st][1], ah_[st][2], ah_[st][3], a + PO_AH);
            ldsm4(al_[st][0], al_[st][1], al_[st][2], al_[st][3], a + PO_AL);
        }
        #pragma unroll
        for (int st = 0; st < 4; st++) {
            #pragma unroll
            for (int g = 0; g < 4; g++) {
                uint32_t off = sw128((uint32_t)((16 * g + krow) * 128 + (2 * st + kseg) * 16));
                uint32_t b0, b1, b2, b3;
                ldsm4(b0, b1, b2, b3, sb + PO_BH + off);
                mmabf(acc[2 * g], ah_[st], b0, b1);
                mmabf(acc[2 * g + 1], ah_[st], b2, b3);
                mmabf(acc[2 * g], al_[st], b0, b1);
                mmabf(acc[2 * g + 1], al_[st], b2, b3);
                uint32_t c0, c1, c2, c3;
                ldsm4(c0, c1, c2, c3, sb + PO_BL + off);
                mmabf(acc[2 * g], ah_[st], c0, c1);
                mmabf(acc[2 * g + 1], ah_[st], c2, c3);
            }
        }
        __syncthreads();
    }

    // epilogue: +bias, relu
    int row0 = r0c + 16 * w + (l >> 2);
    #pragma unroll
    for (int nf = 0; nf < 8; nf++) {
        int col = n0 + 8 * nf + 2 * (l & 3);
        float bx = bias[col], by = bias[col + 1];
        float2 t0 = make_float2(fmaxf(acc[nf][0] + bx, 0.f), fmaxf(acc[nf][1] + by, 0.f));
        float2 t1 = make_float2(fmaxf(acc[nf][2] + bx, 0.f), fmaxf(acc[nf][3] + by, 0.f));
        *(float2*)(out + (size_t)row0 * HID + col) = t0;
        *(float2*)(out + (size_t)(row0 + 8) * HID + col) = t1;
    }
}

// ---------------- launch ----------------
extern "C" void kernel_launch(void* const* d_in, const int* in_sizes, int n_in,
                              void* d_out, int out_size)
{
    const float* q    = (const float*)d_in[0];
    const float* ek   = (const float*)d_in[1];
    const float* ev   = (const float*)d_in[2];
    const float* mask = (const float*)d_in[3];
    const float* wo_w = (const float*)d_in[4];
    const float* wo_b = (const float*)d_in[5];
    float* out = (float*)d_out;

    cudaFuncSetAttribute(attn_tc, cudaFuncAttributeMaxDynamicSharedMemorySize, ATT_SMEM);
    cudaFuncSetAttribute(proj_tc, cudaFuncAttributeMaxDynamicSharedMemorySize, PROJ_SMEM);

    zero_flag_k<<<1, 1>>>();
    scan_mask_k<<<1024, 256>>>(mask, NB * T2 * T2 / 4);

    int blkQ = (NB * T1 * HID / 2) / 256;
    __nv_bfloat16 *qhi, *qlo, *khi, *klo, *vhi, *vlo, *whi, *wlo;
    cudaGetSymbolAddress((void**)&qhi, g_qhi);
    cudaGetSymbolAddress((void**)&qlo, g_qlo);
    cudaGetSymbolAddress((void**)&khi, g_khi);
    cudaGetSymbolAddress((void**)&klo, g_klo);
    cudaGetSymbolAddress((void**)&vhi, g_vhi);
    cudaGetSymbolAddress((void**)&vlo, g_vlo);
    cudaGetSymbolAddress((void**)&whi, g_whi);
    cudaGetSymbolAddress((void**)&wlo, g_wlo);

    split2_k<<<blkQ, 256>>>(q,  qhi, qlo);
    split2_k<<<blkQ, 256>>>(ek, khi, klo);
    split2_k<<<blkQ, 256>>>(ev, vhi, vlo);
    split2_k<<<(HID * HID / 2) / 256, 256>>>(wo_w, whi, wlo);

    dim3 gA(T1 / 128, BH);
    attn_tc<<<gA, 256, ATT_SMEM>>>(mask);

    dim3 gP(NB * T1 / 128, HID / 64);
    proj_tc<<<gP, 256, PROJ_SMEM>>>(wo_b, out);
}

// round 5
// speedup vs baseline: 3.4277x; 1.0097x over previous
#include <cuda_runtime.h>
#include <cuda_bf16.h>
#include <cstdint>

#define HEADS 16
#define DH    64
#define NB    2
#define T1    2048
#define T2    2048
#define HID   1024
#define BH    (NB*HEADS)

// ---------------- device scratch ----------------
__device__ __nv_bfloat16 g_qhi[(size_t)NB * T1 * HID];
__device__ __nv_bfloat16 g_qlo[(size_t)NB * T1 * HID];
__device__ __nv_bfloat16 g_khi[(size_t)NB * T2 * HID];
__device__ __nv_bfloat16 g_klo[(size_t)NB * T2 * HID];
__device__ __nv_bfloat16 g_vhi[(size_t)NB * T2 * HID];
__device__ __nv_bfloat16 g_vlo[(size_t)NB * T2 * HID];
__device__ __nv_bfloat16 g_whi[(size_t)HID * HID];
__device__ __nv_bfloat16 g_wlo[(size_t)HID * HID];
__device__ __nv_bfloat16 g_chi[(size_t)NB * T1 * HID];
__device__ __nv_bfloat16 g_clo[(size_t)NB * T1 * HID];
__device__ int g_mask_flag;

// ---------------- helpers ----------------
__device__ __forceinline__ uint32_t smem_u32(const void* p) {
    uint32_t a;
    asm("{ .reg .u64 t; cvta.to.shared.u64 t, %1; cvt.u32.u64 %0, t; }" : "=r"(a) : "l"(p));
    return a;
}
__device__ __forceinline__ uint32_t sw128(uint32_t o) { return o ^ ((o >> 3) & 0x70); }

__device__ __forceinline__ float bf16r(float x) { return __bfloat162float(__float2bfloat16(x)); }
__device__ __forceinline__ uint32_t packbf2(float lo, float hi) {
    uint32_t r;
    asm("cvt.rn.bf16x2.f32 %0, %1, %2;" : "=r"(r) : "f"(hi), "f"(lo));
    return r;
}
__device__ __forceinline__ void packsplit(float x, float y, uint32_t& hi, uint32_t& lo) {
    float hx = bf16r(x), hy = bf16r(y);
    hi = packbf2(hx, hy);
    lo = packbf2(x - hx, y - hy);
}

__device__ __forceinline__ void ldsm4(uint32_t& r0, uint32_t& r1, uint32_t& r2, uint32_t& r3, uint32_t a) {
    asm volatile("ldmatrix.sync.aligned.m8n8.x4.shared.b16 {%0,%1,%2,%3}, [%4];"
        : "=r"(r0), "=r"(r1), "=r"(r2), "=r"(r3) : "r"(a));
}
__device__ __forceinline__ void ldsm4t(uint32_t& r0, uint32_t& r1, uint32_t& r2, uint32_t& r3, uint32_t a) {
    asm volatile("ldmatrix.sync.aligned.m8n8.x4.trans.shared.b16 {%0,%1,%2,%3}, [%4];"
        : "=r"(r0), "=r"(r1), "=r"(r2), "=r"(r3) : "r"(a));
}
__device__ __forceinline__ void mmabf(float* c, const uint32_t* a, uint32_t b0, uint32_t b1) {
    asm volatile("mma.sync.aligned.m16n8k16.row.col.f32.bf16.bf16.f32 "
        "{%0,%1,%2,%3}, {%4,%5,%6,%7}, {%8,%9}, {%0,%1,%2,%3};"
        : "+f"(c[0]), "+f"(c[1]), "+f"(c[2]), "+f"(c[3])
        : "r"(a[0]), "r"(a[1]), "r"(a[2]), "r"(a[3]), "r"(b0), "r"(b1));
}

#define CP16(dst, src) asm volatile("cp.async.cg.shared.global [%0], [%1], 16;" :: "r"(dst), "l"(src) : "memory")
#define CP_COMMIT()    asm volatile("cp.async.commit_group;" ::: "memory")
#define CP_WAIT1()     asm volatile("cp.async.wait_group 1;" ::: "memory")
#define CP_WAIT0()     asm volatile("cp.async.wait_group 0;" ::: "memory")

// ---------------- mask scan ----------------
__global__ void zero_flag_k() { g_mask_flag = 0; }
__global__ void scan_mask_k(const float* __restrict__ m, int n4) {
    int i = blockIdx.x * blockDim.x + threadIdx.x;
    bool nz = false;
    for (int idx = i; idx < n4; idx += gridDim.x * blockDim.x) {
        float4 v = ((const float4*)m)[idx];
        nz |= (v.x != 0.f) || (v.y != 0.f) || (v.z != 0.f) || (v.w != 0.f);
    }
    if (nz) atomicOr(&g_mask_flag, 1);
}

// ---------------- prep: fp32 -> bf16 hi/lo ----------------
__global__ __launch_bounds__(256) void split3_k(const float* __restrict__ q,
                                                const float* __restrict__ k,
                                                const float* __restrict__ v) {
    size_t i = (size_t)blockIdx.x * 256 + threadIdx.x;
    int which = blockIdx.y;
    const float* src = which == 0 ? q : (which == 1 ? k : v);
    __nv_bfloat16* hi = which == 0 ? g_qhi : (which == 1 ? g_khi : g_vhi);
    __nv_bfloat16* lo = which == 0 ? g_qlo : (which == 1 ? g_klo : g_vlo);
    float2 u = ((const float2*)src)[i];
    float h0 = bf16r(u.x), h1 = bf16r(u.y);
    ((uint32_t*)hi)[i] = packbf2(h0, h1);
    ((uint32_t*)lo)[i] = packbf2(u.x - h0, u.y - h1);
}
__global__ __launch_bounds__(256) void split2_k(const float* __restrict__ src,
                                                __nv_bfloat16* __restrict__ hi,
                                                __nv_bfloat16* __restrict__ lo) {
    size_t i = (size_t)blockIdx.x * 256 + threadIdx.x;
    float2 u = ((const float2*)src)[i];
    float h0 = bf16r(u.x), h1 = bf16r(u.y);
    ((uint32_t*)hi)[i] = packbf2(h0, h1);
    ((uint32_t*)lo)[i] = packbf2(u.x - h0, u.y - h1);
}

// ---------------- attention (FA2 on mma.sync bf16x3) ----------------
// smem: three 32KB buffers (KH|KL|VH|VL, 8KB each, 64 rows x 128B, sw128), +1KB align pad
#define AT_BUF   32768
#define AO_KH    0
#define AO_KL    8192
#define AO_VH    16384
#define AO_VL    24576
#define ATT_SMEM (3 * AT_BUF + 1024)

__device__ __forceinline__ void issue_tile(uint32_t sbuf, int k0, int tid,
    const __nv_bfloat16* khg, const __nv_bfloat16* klg,
    const __nv_bfloat16* vhg, const __nv_bfloat16* vlg)
{
    #pragma unroll
    for (int j = 0; j < 2; j++) {
        int i = tid * 2 + j;
        int row = i >> 3, seg = i & 7;
        uint32_t dsw = sw128((uint32_t)(row * 128 + seg * 16));
        size_t roff = (size_t)(k0 + row) * HID + seg * 8;
        CP16(sbuf + AO_KH + dsw, khg + roff);
        CP16(sbuf + AO_KL + dsw, klg + roff);
        CP16(sbuf + AO_VH + dsw, vhg + roff);
        CP16(sbuf + AO_VL + dsw, vlg + roff);
    }
}

__global__ __launch_bounds__(256, 2) void attn_tc(const float* __restrict__ mask)
{
    extern __shared__ char smraw[];
    uint32_t sb0 = smem_u32(smraw);
    uint32_t pad = (1024u - (sb0 & 1023u)) & 1023u;
    char* smp = smraw + pad;
    uint32_t sb = sb0 + pad;

    const int tid = threadIdx.x;
    const int w = tid >> 5, l = tid & 31;
    const int bh = blockIdx.y, b = bh >> 4, h = bh & 15;
    const int q0 = blockIdx.x * 128;

    const __nv_bfloat16* khg = g_khi + (size_t)b * T2 * HID + h * DH;
    const __nv_bfloat16* klg = g_klo + (size_t)b * T2 * HID + h * DH;
    const __nv_bfloat16* vhg = g_vhi + (size_t)b * T2 * HID + h * DH;
    const __nv_bfloat16* vlg = g_vlo + (size_t)b * T2 * HID + h * DH;

    // ---- load Q fragments (persist in registers), staged through buf0 (before cp pipeline) ----
    uint32_t qh_[4][4], ql_[4][4];
    {
        const __nv_bfloat16* qhg = g_qhi + ((size_t)b * T1 + q0) * HID + h * DH;
        const __nv_bfloat16* qlg = g_qlo + ((size_t)b * T1 + q0) * HID + h * DH;
        const uint32_t qrow = (uint32_t)(16 * w + (l & 15));
        #pragma unroll
        for (int pass = 0; pass < 2; pass++) {
            const __nv_bfloat16* src = pass ? qlg : qhg;
            #pragma unroll
            for (int j = 0; j < 4; j++) {
                int i = tid * 4 + j;
                int row = i >> 3, seg = i & 7;
                *(uint4*)(smp + sw128((uint32_t)(row * 128 + seg * 16))) =
                    *(const uint4*)(src + (size_t)row * HID + seg * 8);
            }
            __syncthreads();
            #pragma unroll
            for (int st = 0; st < 4; st++) {
                uint32_t a = sb + sw128(qrow * 128 + (uint32_t)(2 * st + (l >> 4)) * 16);
                if (pass == 0) ldsm4(qh_[st][0], qh_[st][1], qh_[st][2], qh_[st][3], a);
                else           ldsm4(ql_[st][0], ql_[st][1], ql_[st][2], ql_[st][3], a);
            }
            __syncthreads();
        }
    }

    // kick off tiles 0,1 into bufs 0,1
    issue_tile(sb, 0, tid, khg, klg, vhg, vlg);
    CP_COMMIT();
    issue_tile(sb + AT_BUF, 64, tid, khg, klg, vhg, vlg);
    CP_COMMIT();

    const bool use_mask = (g_mask_flag != 0);
    const float* mr0 = mask + ((size_t)b * T2 + (q0 + 16 * w + (l >> 2))) * T2;
    const float* mr1 = mr0 + (size_t)8 * T2;

    // ldmatrix per-thread address components
    const uint32_t krow = (uint32_t)((l & 7) + ((l & 16) >> 1)); // + 16*g
    const uint32_t kseg = (uint32_t)((l >> 3) & 1);              // + 2*st
    const uint32_t vrow = (uint32_t)((l & 7) + (l & 8));         // + 16*st
    const uint32_t vseg = (uint32_t)(l >> 4);                    // + 2*g

    float o_[8][4];
    #pragma unroll
    for (int i = 0; i < 8; i++)
        #pragma unroll
        for (int j = 0; j < 4; j++) o_[i][j] = 0.f;
    float m0 = -1e30f, m1 = -1e30f, l0 = 0.f, l1 = 0.f;

    int ci = 0, ii = 2;   // current buf, issue buf (rotating mod 3)
    for (int kt = 0; kt < 32; kt++) {
        if (kt == 31) { CP_WAIT0(); } else { CP_WAIT1(); }
        __syncthreads();
        if (kt + 2 < 32) {
            issue_tile(sb + (uint32_t)ii * AT_BUF, (kt + 2) * 64, tid, khg, klg, vhg, vlg);
            CP_COMMIT();
        }
        uint32_t cur = sb + (uint32_t)ci * AT_BUF;
        ci = (ci == 2) ? 0 : ci + 1;
        ii = (ii == 2) ? 0 : ii + 1;

        // ---- S = Qhi*Khi + Qhi*Klo + Qlo*Khi ----
        float s_[8][4];
        #pragma unroll
        for (int i = 0; i < 8; i++)
            #pragma unroll
            for (int j = 0; j < 4; j++) s_[i][j] = 0.f;

        #pragma unroll
        for (int st = 0; st < 4; st++) {
            #pragma unroll
            for (int g = 0; g < 4; g++) {
                uint32_t off = sw128((uint32_t)((16 * g + krow) * 128 + (2 * st + kseg) * 16));
                uint32_t b0, b1, b2, b3;
                ldsm4(b0, b1, b2, b3, cur + AO_KH + off);
                mmabf(s_[2 * g], qh_[st], b0, b1);
                mmabf(s_[2 * g + 1], qh_[st], b2, b3);
                mmabf(s_[2 * g], ql_[st], b0, b1);
                mmabf(s_[2 * g + 1], ql_[st], b2, b3);
                uint32_t c0, c1, c2, c3;
                ldsm4(c0, c1, c2, c3, cur + AO_KL + off);
                mmabf(s_[2 * g], qh_[st], c0, c1);
                mmabf(s_[2 * g + 1], qh_[st], c2, c3);
            }
        }

        if (use_mask) {
            int k0 = kt * 64;
            #pragma unroll
            for (int nf = 0; nf < 8; nf++) {
                float2 a = *(const float2*)(mr0 + k0 + 8 * nf + 2 * (l & 3));
                float2 c = *(const float2*)(mr1 + k0 + 8 * nf + 2 * (l & 3));
                s_[nf][0] += a.x; s_[nf][1] += a.y;
                s_[nf][2] += c.x; s_[nf][3] += c.y;
            }
        }

        // ---- online softmax (rows t/4 and t/4+8) ----
        float mt0 = -1e30f, mt1 = -1e30f;
        #pragma unroll
        for (int nf = 0; nf < 8; nf++) {
            mt0 = fmaxf(mt0, fmaxf(s_[nf][0], s_[nf][1]));
            mt1 = fmaxf(mt1, fmaxf(s_[nf][2], s_[nf][3]));
        }
        mt0 = fmaxf(mt0, __shfl_xor_sync(0xffffffffu, mt0, 1));
        mt0 = fmaxf(mt0, __shfl_xor_sync(0xffffffffu, mt0, 2));
        mt1 = fmaxf(mt1, __shfl_xor_sync(0xffffffffu, mt1, 1));
        mt1 = fmaxf(mt1, __shfl_xor_sync(0xffffffffu, mt1, 2));
        float nm0 = fmaxf(m0, mt0), nm1 = fmaxf(m1, mt1);
        float cr0 = __expf(m0 - nm0), cr1 = __expf(m1 - nm1);
        m0 = nm0; m1 = nm1;
        float sum0 = 0.f, sum1 = 0.f;
        #pragma unroll
        for (int nf = 0; nf < 8; nf++) {
            s_[nf][0] = __expf(s_[nf][0] - nm0); sum0 += s_[nf][0];
            s_[nf][1] = __expf(s_[nf][1] - nm0); sum0 += s_[nf][1];
            s_[nf][2] = __expf(s_[nf][2] - nm1); sum1 += s_[nf][2];
            s_[nf][3] = __expf(s_[nf][3] - nm1); sum1 += s_[nf][3];
        }
        sum0 += __shfl_xor_sync(0xffffffffu, sum0, 1);
        sum0 += __shfl_xor_sync(0xffffffffu, sum0, 2);
        sum1 += __shfl_xor_sync(0xffffffffu, sum1, 1);
        sum1 += __shfl_xor_sync(0xffffffffu, sum1, 2);
        l0 = l0 * cr0 + sum0;
        l1 = l1 * cr1 + sum1;
        #pragma unroll
        for (int nf = 0; nf < 8; nf++) {
            o_[nf][0] *= cr0; o_[nf][1] *= cr0;
            o_[nf][2] *= cr1; o_[nf][3] *= cr1;
        }

        // ---- pack P -> A fragments (hi/lo), pure register shuffle ----
        uint32_t ph_[4][4], pl_[4][4];
        #pragma unroll
        for (int st = 0; st < 4; st++) {
            packsplit(s_[2 * st][0],     s_[2 * st][1],     ph_[st][0], pl_[st][0]);
            packsplit(s_[2 * st][2],     s_[2 * st][3],     ph_[st][1], pl_[st][1]);
            packsplit(s_[2 * st + 1][0], s_[2 * st + 1][1], ph_[st][2], pl_[st][2]);
            packsplit(s_[2 * st + 1][2], s_[2 * st + 1][3], ph_[st][3], pl_[st][3]);
        }

        // ---- O += Phi*Vhi + Plo*Vhi + Phi*Vlo ----
        #pragma unroll
        for (int st = 0; st < 4; st++) {
            #pragma unroll
            for (int g = 0; g < 4; g++) {
                uint32_t off = sw128((uint32_t)((16 * st + vrow) * 128 + (2 * g + vseg) * 16));
                uint32_t b0, b1, b2, b3;
                ldsm4t(b0, b1, b2, b3, cur + AO_VH + off);
                mmabf(o_[2 * g], ph_[st], b0, b1);
                mmabf(o_[2 * g + 1], ph_[st], b2, b3);
                mmabf(o_[2 * g], pl_[st], b0, b1);
                mmabf(o_[2 * g + 1], pl_[st], b2, b3);
                uint32_t c0, c1, c2, c3;
                ldsm4t(c0, c1, c2, c3, cur + AO_VL + off);
                mmabf(o_[2 * g], ph_[st], c0, c1);
                mmabf(o_[2 * g + 1], ph_[st], c2, c3);
            }
        }
    }

    // ---- epilogue: normalize, split to bf16 hi/lo ctx ----
    float inv0 = 1.0f / l0, inv1 = 1.0f / l1;
    int r0 = q0 + 16 * w + (l >> 2);
    size_t base0 = ((size_t)b * T1 + r0) * HID + h * DH;
    size_t base1 = base0 + (size_t)8 * HID;
    #pragma unroll
    for (int nf = 0; nf < 8; nf++) {
        int col = 8 * nf + 2 * (l & 3);
        uint32_t hi, lo;
        packsplit(o_[nf][0] * inv0, o_[nf][1] * inv0, hi, lo);
        *(uint32_t*)(g_chi + base0 + col) = hi;
        *(uint32_t*)(g_clo + base0 + col) = lo;
        packsplit(o_[nf][2] * inv1, o_[nf][3] * inv1, hi, lo);
        *(uint32_t*)(g_chi + base1 + col) = hi;
        *(uint32_t*)(g_clo + base1 + col) = lo;
    }
}

// ---------------- proj: out = relu(ctx @ W^T + b), mma bf16x3, double-buffered ----------------
#define PB_AH 0
#define PB_AL 16384
#define PB_BH 32768
#define PB_BL 40960
#define PB_SZ 49152
#define PROJ_SMEM (2 * PB_SZ + 1024)

__device__ __forceinline__ void proj_issue(uint32_t sbuf, int r0c, int n0, int e0, int tid)
{
    #pragma unroll
    for (int j = 0; j < 4; j++) {
        int i = tid * 4 + j;
        int row = i >> 3, seg = i & 7;
        uint32_t dsw = sw128((uint32_t)(row * 128 + seg * 16));
        size_t roff = (size_t)(r0c + row) * HID + e0 + seg * 8;
        CP16(sbuf + PB_AH + dsw, g_chi + roff);
        CP16(sbuf + PB_AL + dsw, g_clo + roff);
    }
    #pragma unroll
    for (int j = 0; j < 2; j++) {
        int i = tid * 2 + j;
        int row = i >> 3, seg = i & 7;
        uint32_t dsw = sw128((uint32_t)(row * 128 + seg * 16));
        size_t roff = (size_t)(n0 + row) * HID + e0 + seg * 8;
        CP16(sbuf + PB_BH + dsw, g_whi + roff);
        CP16(sbuf + PB_BL + dsw, g_wlo + roff);
    }
}

__global__ __launch_bounds__(256, 2) void proj_tc(const float* __restrict__ bias,
                                                  float* __restrict__ out)
{
    extern __shared__ char smraw[];
    uint32_t sb0 = smem_u32(smraw);
    uint32_t pad = (1024u - (sb0 & 1023u)) & 1023u;
    uint32_t sb = sb0 + pad;

    const int tid = threadIdx.x;
    const int w = tid >> 5, l = tid & 31;
    const int r0c = blockIdx.x * 128, n0 = blockIdx.y * 64;

    const uint32_t arow = (uint32_t)(16 * w + (l & 15));
    const uint32_t aseg = (uint32_t)(l >> 4);
    const uint32_t krow = (uint32_t)((l & 7) + ((l & 16) >> 1));
    const uint32_t kseg = (uint32_t)((l >> 3) & 1);

    float acc[8][4];
    #pragma unroll
    for (int i = 0; i < 8; i++)
        #pragma unroll
        for (int j = 0; j < 4; j++) acc[i][j] = 0.f;

    proj_issue(sb, r0c, n0, 0, tid);
    CP_COMMIT();

    for (int c = 0; c < 16; c++) {
        CP_WAIT0();
        __syncthreads();
        uint32_t cur = sb + (uint32_t)(c & 1) * PB_SZ;
        if (c + 1 < 16) {
            proj_issue(sb + (uint32_t)((c + 1) & 1) * PB_SZ, r0c, n0, (c + 1) * 64, tid);
            CP_COMMIT();
        }

        uint32_t ah_[4][4], al_[4][4];
        #pragma unroll
        for (int st = 0; st < 4; st++) {
            uint32_t a = cur + sw128(arow * 128 + (uint32_t)(2 * st + aseg) * 16);
            ldsm4(ah_[st][0], ah_[st][1], ah_[st][2], ah_[st][3], a + PB_AH);
            ldsm4(al_[st][0], al_[st][1], al_[st][2], al_[st][3], a + PB_AL);
        }
        #pragma unroll
        for (int st = 0; st < 4; st++) {
            #pragma unroll
            for (int g = 0; g < 4; g++) {
                uint32_t off = sw128((uint32_t)((16 * g + krow) * 128 + (2 * st + kseg) * 16));
                uint32_t b0, b1, b2, b3;
                ldsm4(b0, b1, b2, b3, cur + PB_BH + off);
                mmabf(acc[2 * g], ah_[st], b0, b1);
                mmabf(acc[2 * g + 1], ah_[st], b2, b3);
                mmabf(acc[2 * g], al_[st], b0, b1);
                mmabf(acc[2 * g + 1], al_[st], b2, b3);
                uint32_t c0, c1, c2, c3;
                ldsm4(c0, c1, c2, c3, cur + PB_BL + off);
                mmabf(acc[2 * g], ah_[st], c0, c1);
                mmabf(acc[2 * g + 1], ah_[st], c2, c3);
            }
        }
        __syncthreads();
    }

    // epilogue: +bias, relu
    int row0 = r0c + 16 * w + (l >> 2);
    #pragma unroll
    for (int nf = 0; nf < 8; nf++) {
        int col = n0 + 8 * nf + 2 * (l & 3);
        float bx = bias[col], by = bias[col + 1];
        float2 t0 = make_float2(fmaxf(acc[nf][0] + bx, 0.f), fmaxf(acc[nf][1] + by, 0.f));
        float2 t1 = make_float2(fmaxf(acc[nf][2] + bx, 0.f), fmaxf(acc[nf][3] + by, 0.f));
        *(float2*)(out + (size_t)row0 * HID + col) = t0;
        *(float2*)(out + (size_t)(row0 + 8) * HID + col) = t1;
    }
}

// ---------------- launch ----------------
extern "C" void kernel_launch(void* const* d_in, const int* in_sizes, int n_in,
                              void* d_out, int out_size)
{
    const float* q    = (const float*)d_in[0];
    const float* ek   = (const float*)d_in[1];
    const float* ev   = (const float*)d_in[2];
    const float* mask = (const float*)d_in[3];
    const float* wo_w = (const float*)d_in[4];
    const float* wo_b = (const float*)d_in[5];
    float* out = (float*)d_out;

    cudaFuncSetAttribute(attn_tc, cudaFuncAttributeMaxDynamicSharedMemorySize, ATT_SMEM);
    cudaFuncSetAttribute(proj_tc, cudaFuncAttributeMaxDynamicSharedMemorySize, PROJ_SMEM);

    zero_flag_k<<<1, 1>>>();
    scan_mask_k<<<1024, 256>>>(mask, NB * T2 * T2 / 4);

    __nv_bfloat16 *whi, *wlo;
    cudaGetSymbolAddress((void**)&whi, g_whi);
    cudaGetSymbolAddress((void**)&wlo, g_wlo);

    dim3 gS((NB * T1 * HID / 2) / 256, 3);
    split3_k<<<gS, 256>>>(q, ek, ev);
    split2_k<<<(HID * HID / 2) / 256, 256>>>(wo_w, whi, wlo);

    dim3 gA(T1 / 128, BH);
    attn_tc<<<gA, 256, ATT_SMEM>>>(mask);

    dim3 gP(NB * T1 / 128, HID / 64);
    proj_tc<<<gP, 256, PROJ_SMEM>>>(wo_b, out);
}

// round 7
// speedup vs baseline: 4.0240x; 1.1740x over previous
#include <cuda_runtime.h>
#include <cuda_bf16.h>
#include <cuda_fp16.h>
#include <cstdint>

#define HEADS 16
#define DH    64
#define NB    2
#define T1    2048
#define T2    2048
#define HID   1024
#define BH    (NB*HEADS)

// ---------------- device scratch ----------------
__device__ __nv_bfloat16 g_qhi[(size_t)NB * T1 * HID];
__device__ __nv_bfloat16 g_qlo[(size_t)NB * T1 * HID];
__device__ __nv_bfloat16 g_khi[(size_t)NB * T2 * HID];
__device__ __nv_bfloat16 g_klo[(size_t)NB * T2 * HID];
__device__ __half        g_vf [(size_t)NB * T2 * HID];   // V, single fp16
__device__ __half        g_wf [(size_t)HID * HID];       // W, single fp16
__device__ __half        g_ch [(size_t)NB * T1 * HID];   // ctx fp16 hi
__device__ __half        g_cl [(size_t)NB * T1 * HID];   // ctx fp16 lo
__device__ int g_mask_flag;

// ---------------- helpers ----------------
__device__ __forceinline__ uint32_t smem_u32(const void* p) {
    uint32_t a;
    asm("{ .reg .u64 t; cvta.to.shared.u64 t, %1; cvt.u32.u64 %0, t; }" : "=r"(a) : "l"(p));
    return a;
}
__device__ __forceinline__ uint32_t sw128(uint32_t o) { return o ^ ((o >> 3) & 0x70); }

__device__ __forceinline__ float bf16r(float x) { return __bfloat162float(__float2bfloat16(x)); }
__device__ __forceinline__ uint32_t packbf2(float lo, float hi) {
    uint32_t r;
    asm("cvt.rn.bf16x2.f32 %0, %1, %2;" : "=r"(r) : "f"(hi), "f"(lo));
    return r;
}
// fp16 split of a float pair: hi = rn(x), lo = rn(x - hi); packed as f16x2
__device__ __forceinline__ void packsplit_h(float x, float y, uint32_t& hi, uint32_t& lo) {
    __half hx = __float2half_rn(x), hy = __float2half_rn(y);
    __half2 H = __halves2half2(hx, hy);
    __half2 L = __halves2half2(__float2half_rn(x - __half2float(hx)),
                               __float2half_rn(y - __half2float(hy)));
    hi = *(uint32_t*)&H;
    lo = *(uint32_t*)&L;
}

__device__ __forceinline__ void ldsm4(uint32_t& r0, uint32_t& r1, uint32_t& r2, uint32_t& r3, uint32_t a) {
    asm volatile("ldmatrix.sync.aligned.m8n8.x4.shared.b16 {%0,%1,%2,%3}, [%4];"
        : "=r"(r0), "=r"(r1), "=r"(r2), "=r"(r3) : "r"(a));
}
__device__ __forceinline__ void ldsm4t(uint32_t& r0, uint32_t& r1, uint32_t& r2, uint32_t& r3, uint32_t a) {
    asm volatile("ldmatrix.sync.aligned.m8n8.x4.trans.shared.b16 {%0,%1,%2,%3}, [%4];"
        : "=r"(r0), "=r"(r1), "=r"(r2), "=r"(r3) : "r"(a));
}
__device__ __forceinline__ void mmabf(float* c, const uint32_t* a, uint32_t b0, uint32_t b1) {
    asm volatile("mma.sync.aligned.m16n8k16.row.col.f32.bf16.bf16.f32 "
        "{%0,%1,%2,%3}, {%4,%5,%6,%7}, {%8,%9}, {%0,%1,%2,%3};"
        : "+f"(c[0]), "+f"(c[1]), "+f"(c[2]), "+f"(c[3])
        : "r"(a[0]), "r"(a[1]), "r"(a[2]), "r"(a[3]), "r"(b0), "r"(b1));
}
__device__ __forceinline__ void mmafp(float* c, const uint32_t* a, uint32_t b0, uint32_t b1) {
    asm volatile("mma.sync.aligned.m16n8k16.row.col.f32.f16.f16.f32 "
        "{%0,%1,%2,%3}, {%4,%5,%6,%7}, {%8,%9}, {%0,%1,%2,%3};"
        : "+f"(c[0]), "+f"(c[1]), "+f"(c[2]), "+f"(c[3])
        : "r"(a[0]), "r"(a[1]), "r"(a[2]), "r"(a[3]), "r"(b0), "r"(b1));
}

#define CP16(dst, src) asm volatile("cp.async.cg.shared.global [%0], [%1], 16;" :: "r"(dst), "l"(src) : "memory")
#define CP_COMMIT()    asm volatile("cp.async.commit_group;" ::: "memory")
#define CP_WAIT1()     asm volatile("cp.async.wait_group 1;" ::: "memory")
#define CP_WAIT0()     asm volatile("cp.async.wait_group 0;" ::: "memory")

// ---------------- mask scan ----------------
__global__ void zero_flag_k() { g_mask_flag = 0; }
__global__ void scan_mask_k(const float* __restrict__ m, int n4) {
    int i = blockIdx.x * blockDim.x + threadIdx.x;
    bool nz = false;
    for (int idx = i; idx < n4; idx += gridDim.x * blockDim.x) {
        float4 v = ((const float4*)m)[idx];
        nz |= (v.x != 0.f) || (v.y != 0.f) || (v.z != 0.f) || (v.w != 0.f);
    }
    if (nz) atomicOr(&g_mask_flag, 1);
}

// ---------------- prep: q,k -> bf16 hi/lo ; v -> fp16 ----------------
__global__ __launch_bounds__(256) void split3_k(const float* __restrict__ q,
                                                const float* __restrict__ k,
                                                const float* __restrict__ v) {
    size_t i = (size_t)blockIdx.x * 256 + threadIdx.x;
    int which = blockIdx.y;
    if (which == 2) {
        float2 u = ((const float2*)v)[i];
        ((__half2*)g_vf)[i] = __floats2half2_rn(u.x, u.y);
        return;
    }
    const float* src = which == 0 ? q : k;
    __nv_bfloat16* hi = which == 0 ? g_qhi : g_khi;
    __nv_bfloat16* lo = which == 0 ? g_qlo : g_klo;
    float2 u = ((const float2*)src)[i];
    float h0 = bf16r(u.x), h1 = bf16r(u.y);
    ((uint32_t*)hi)[i] = packbf2(h0, h1);
    ((uint32_t*)lo)[i] = packbf2(u.x - h0, u.y - h1);
}
__global__ __launch_bounds__(256) void convw_k(const float* __restrict__ w) {
    size_t i = (size_t)blockIdx.x * 256 + threadIdx.x;
    float2 u = ((const float2*)w)[i];
    ((__half2*)g_wf)[i] = __floats2half2_rn(u.x, u.y);
}

// ---------------- attention (FA2; S = bf16x3, PV = fp16x2) ----------------
// smem buffer: KH | KL | VF, 8KB each (64 rows x 128B, sw128); 3 buffers
#define AT_BUF   24576
#define AO_KH    0
#define AO_KL    8192
#define AO_VF    16384
#define ATT_SMEM (3 * AT_BUF + 1024)

__device__ __forceinline__ void issue_tile(uint32_t sbuf, int k0, int tid,
    const __nv_bfloat16* khg, const __nv_bfloat16* klg, const __half* vfg)
{
    #pragma unroll
    for (int j = 0; j < 2; j++) {
        int i = tid * 2 + j;
        int row = i >> 3, seg = i & 7;
        uint32_t dsw = sw128((uint32_t)(row * 128 + seg * 16));
        size_t roff = (size_t)(k0 + row) * HID + seg * 8;
        CP16(sbuf + AO_KH + dsw, khg + roff);
        CP16(sbuf + AO_KL + dsw, klg + roff);
        CP16(sbuf + AO_VF + dsw, vfg + roff);
    }
}

__global__ __launch_bounds__(256, 2) void attn_tc(const float* __restrict__ mask)
{
    extern __shared__ char smraw[];
    uint32_t sb0 = smem_u32(smraw);
    uint32_t pad = (1024u - (sb0 & 1023u)) & 1023u;
    char* smp = smraw + pad;
    uint32_t sb = sb0 + pad;

    const int tid = threadIdx.x;
    const int w = tid >> 5, l = tid & 31;
    const int bh = blockIdx.y, b = bh >> 4, h = bh & 15;
    const int q0 = blockIdx.x * 128;

    const __nv_bfloat16* khg = g_khi + (size_t)b * T2 * HID + h * DH;
    const __nv_bfloat16* klg = g_klo + (size_t)b * T2 * HID + h * DH;
    const __half*        vfg = g_vf  + (size_t)b * T2 * HID + h * DH;

    // ---- load Q fragments (persist in registers), staged through buf0 ----
    uint32_t qh_[4][4], ql_[4][4];
    {
        const __nv_bfloat16* qhg = g_qhi + ((size_t)b * T1 + q0) * HID + h * DH;
        const __nv_bfloat16* qlg = g_qlo + ((size_t)b * T1 + q0) * HID + h * DH;
        const uint32_t qrow = (uint32_t)(16 * w + (l & 15));
        #pragma unroll
        for (int pass = 0; pass < 2; pass++) {
            const __nv_bfloat16* src = pass ? qlg : qhg;
            #pragma unroll
            for (int j = 0; j < 4; j++) {
                int i = tid * 4 + j;
                int row = i >> 3, seg = i & 7;
                *(uint4*)(smp + sw128((uint32_t)(row * 128 + seg * 16))) =
                    *(const uint4*)(src + (size_t)row * HID + seg * 8);
            }
            __syncthreads();
            #pragma unroll
            for (int st = 0; st < 4; st++) {
                uint32_t a = sb + sw128(qrow * 128 + (uint32_t)(2 * st + (l >> 4)) * 16);
                if (pass == 0) ldsm4(qh_[st][0], qh_[st][1], qh_[st][2], qh_[st][3], a);
                else           ldsm4(ql_[st][0], ql_[st][1], ql_[st][2], ql_[st][3], a);
            }
            __syncthreads();
        }
    }

    // kick off tiles 0,1 into bufs 0,1
    issue_tile(sb, 0, tid, khg, klg, vfg);
    CP_COMMIT();
    issue_tile(sb + AT_BUF, 64, tid, khg, klg, vfg);
    CP_COMMIT();

    const bool use_mask = (g_mask_flag != 0);
    const float* mr0 = mask + ((size_t)b * T2 + (q0 + 16 * w + (l >> 2))) * T2;
    const float* mr1 = mr0 + (size_t)8 * T2;

    const uint32_t krow = (uint32_t)((l & 7) + ((l & 16) >> 1)); // + 16*g
    const uint32_t kseg = (uint32_t)((l >> 3) & 1);              // + 2*st
    const uint32_t vrow = (uint32_t)((l & 7) + (l & 8));         // + 16*st
    const uint32_t vseg = (uint32_t)(l >> 4);                    // + 2*g

    float o_[8][4];
    #pragma unroll
    for (int i = 0; i < 8; i++)
        #pragma unroll
        for (int j = 0; j < 4; j++) o_[i][j] = 0.f;
    float m0 = -1e30f, m1 = -1e30f, l0 = 0.f, l1 = 0.f;

    int ci = 0, ii = 2;
    for (int kt = 0; kt < 32; kt++) {
        if (kt == 31) { CP_WAIT0(); } else { CP_WAIT1(); }
        __syncthreads();
        if (kt + 2 < 32) {
            issue_tile(sb + (uint32_t)ii * AT_BUF, (kt + 2) * 64, tid, khg, klg, vfg);
            CP_COMMIT();
        }
        uint32_t cur = sb + (uint32_t)ci * AT_BUF;
        ci = (ci == 2) ? 0 : ci + 1;
        ii = (ii == 2) ? 0 : ii + 1;

        // ---- S = Qhi*Khi + Qhi*Klo + Qlo*Khi (bf16 x3) ----
        float s_[8][4];
        #pragma unroll
        for (int i = 0; i < 8; i++)
            #pragma unroll
            for (int j = 0; j < 4; j++) s_[i][j] = 0.f;

        #pragma unroll
        for (int st = 0; st < 4; st++) {
            #pragma unroll
            for (int g = 0; g < 4; g++) {
                uint32_t off = sw128((uint32_t)((16 * g + krow) * 128 + (2 * st + kseg) * 16));
                uint32_t b0, b1, b2, b3;
                ldsm4(b0, b1, b2, b3, cur + AO_KH + off);
                mmabf(s_[2 * g], qh_[st], b0, b1);
                mmabf(s_[2 * g + 1], qh_[st], b2, b3);
                mmabf(s_[2 * g], ql_[st], b0, b1);
                mmabf(s_[2 * g + 1], ql_[st], b2, b3);
                uint32_t c0, c1, c2, c3;
                ldsm4(c0, c1, c2, c3, cur + AO_KL + off);
                mmabf(s_[2 * g], qh_[st], c0, c1);
                mmabf(s_[2 * g + 1], qh_[st], c2, c3);
            }
        }

        if (use_mask) {
            int k0 = kt * 64;
            #pragma unroll
            for (int nf = 0; nf < 8; nf++) {
                float2 a = *(const float2*)(mr0 + k0 + 8 * nf + 2 * (l & 3));
                float2 c = *(const float2*)(mr1 + k0 + 8 * nf + 2 * (l & 3));
                s_[nf][0] += a.x; s_[nf][1] += a.y;
                s_[nf][2] += c.x; s_[nf][3] += c.y;
            }
        }

        // ---- online softmax ----
        float mt0 = -1e30f, mt1 = -1e30f;
        #pragma unroll
        for (int nf = 0; nf < 8; nf++) {
            mt0 = fmaxf(mt0, fmaxf(s_[nf][0], s_[nf][1]));
            mt1 = fmaxf(mt1, fmaxf(s_[nf][2], s_[nf][3]));
        }
        mt0 = fmaxf(mt0, __shfl_xor_sync(0xffffffffu, mt0, 1));
        mt0 = fmaxf(mt0, __shfl_xor_sync(0xffffffffu, mt0, 2));
        mt1 = fmaxf(mt1, __shfl_xor_sync(0xffffffffu, mt1, 1));
        mt1 = fmaxf(mt1, __shfl_xor_sync(0xffffffffu, mt1, 2));
        float nm0 = fmaxf(m0, mt0), nm1 = fmaxf(m1, mt1);
        float cr0 = __expf(m0 - nm0), cr1 = __expf(m1 - nm1);
        m0 = nm0; m1 = nm1;
        float sum0 = 0.f, sum1 = 0.f;
        #pragma unroll
        for (int nf = 0; nf < 8; nf++) {
            s_[nf][0] = __expf(s_[nf][0] - nm0); sum0 += s_[nf][0];
            s_[nf][1] = __expf(s_[nf][1] - nm0); sum0 += s_[nf][1];
            s_[nf][2] = __expf(s_[nf][2] - nm1); sum1 += s_[nf][2];
            s_[nf][3] = __expf(s_[nf][3] - nm1); sum1 += s_[nf][3];
        }
        sum0 += __shfl_xor_sync(0xffffffffu, sum0, 1);
        sum0 += __shfl_xor_sync(0xffffffffu, sum0, 2);
        sum1 += __shfl_xor_sync(0xffffffffu, sum1, 1);
        sum1 += __shfl_xor_sync(0xffffffffu, sum1, 2);
        l0 = l0 * cr0 + sum0;
        l1 = l1 * cr1 + sum1;
        #pragma unroll
        for (int nf = 0; nf < 8; nf++) {
            o_[nf][0] *= cr0; o_[nf][1] *= cr0;
            o_[nf][2] *= cr1; o_[nf][3] *= cr1;
        }

        // ---- pack P -> fp16 hi/lo A fragments (P exact to 2^-22) ----
        uint32_t ph_[4][4], pl_[4][4];
        #pragma unroll
        for (int st = 0; st < 4; st++) {
            packsplit_h(s_[2 * st][0],     s_[2 * st][1],     ph_[st][0], pl_[st][0]);
            packsplit_h(s_[2 * st][2],     s_[2 * st][3],     ph_[st][1], pl_[st][1]);
            packsplit_h(s_[2 * st + 1][0], s_[2 * st + 1][1], ph_[st][2], pl_[st][2]);
            packsplit_h(s_[2 * st + 1][2], s_[2 * st + 1][3], ph_[st][3], pl_[st][3]);
        }

        // ---- O += Phi*V + Plo*V  (fp16 x2) ----
        #pragma unroll
        for (int st = 0; st < 4; st++) {
            #pragma unroll
            for (int g = 0; g < 4; g++) {
                uint32_t off = sw128((uint32_t)((16 * st + vrow) * 128 + (2 * g + vseg) * 16));
                uint32_t b0, b1, b2, b3;
                ldsm4t(b0, b1, b2, b3, cur + AO_VF + off);
                mmafp(o_[2 * g], ph_[st], b0, b1);
                mmafp(o_[2 * g + 1], ph_[st], b2, b3);
                mmafp(o_[2 * g], pl_[st], b0, b1);
                mmafp(o_[2 * g + 1], pl_[st], b2, b3);
            }
        }
    }

    // ---- epilogue: normalize, split to fp16 hi/lo ctx ----
    float inv0 = 1.0f / l0, inv1 = 1.0f / l1;
    int r0 = q0 + 16 * w + (l >> 2);
    size_t base0 = ((size_t)b * T1 + r0) * HID + h * DH;
    size_t base1 = base0 + (size_t)8 * HID;
    #pragma unroll
    for (int nf = 0; nf < 8; nf++) {
        int col = 8 * nf + 2 * (l & 3);
        uint32_t hi, lo;
        packsplit_h(o_[nf][0] * inv0, o_[nf][1] * inv0, hi, lo);
        *(uint32_t*)(g_ch + base0 + col) = hi;
        *(uint32_t*)(g_cl + base0 + col) = lo;
        packsplit_h(o_[nf][2] * inv1, o_[nf][3] * inv1, hi, lo);
        *(uint32_t*)(g_ch + base1 + col) = hi;
        *(uint32_t*)(g_cl + base1 + col) = lo;
    }
}

// ---------------- proj: out = relu(ctx @ W^T + b), fp16 x2, double-buffered ----------------
#define PB_AH 0
#define PB_AL 16384
#define PB_W  32768
#define PB_SZ 40960
#define PROJ_SMEM (2 * PB_SZ + 1024)

__device__ __forceinline__ void proj_issue(uint32_t sbuf, int r0c, int n0, int e0, int tid)
{
    #pragma unroll
    for (int j = 0; j < 4; j++) {
        int i = tid * 4 + j;
        int row = i >> 3, seg = i & 7;
        uint32_t dsw = sw128((uint32_t)(row * 128 + seg * 16));
        size_t roff = (size_t)(r0c + row) * HID + e0 + seg * 8;
        CP16(sbuf + PB_AH + dsw, g_ch + roff);
        CP16(sbuf + PB_AL + dsw, g_cl + roff);
    }
    #pragma unroll
    for (int j = 0; j < 2; j++) {
        int i = tid * 2 + j;
        int row = i >> 3, seg = i & 7;
        uint32_t dsw = sw128((uint32_t)(row * 128 + seg * 16));
        size_t roff = (size_t)(n0 + row) * HID + e0 + seg * 8;
        CP16(sbuf + PB_W + dsw, g_wf + roff);
    }
}

__global__ __launch_bounds__(256, 2) void proj_tc(const float* __restrict__ bias,
                                                  float* __restrict__ out)
{
    extern __shared__ char smraw[];
    uint32_t sb0 = smem_u32(smraw);
    uint32_t pad = (1024u - (sb0 & 1023u)) & 1023u;
    uint32_t sb = sb0 + pad;

    const int tid = threadIdx.x;
    const int w = tid >> 5, l = tid & 31;
    const int r0c = blockIdx.x * 128, n0 = blockIdx.y * 64;

    const uint32_t arow = (uint32_t)(16 * w + (l & 15));
    const uint32_t aseg = (uint32_t)(l >> 4);
    const uint32_t krow = (uint32_t)((l & 7) + ((l & 16) >> 1));
    const uint32_t kseg = (uint32_t)((l >> 3) & 1);

    float acc[8][4];
    #pragma unroll
    for (int i = 0; i < 8; i++)
        #pragma unroll
        for (int j = 0; j < 4; j++) acc[i][j] = 0.f;

    proj_issue(sb, r0c, n0, 0, tid);
    CP_COMMIT();

    for (int c = 0; c < 16; c++) {
        CP_WAIT0();
        __syncthreads();
        uint32_t cur = sb + (uint32_t)(c & 1) * PB_SZ;
        if (c + 1 < 16) {
            proj_issue(sb + (uint32_t)((c + 1) & 1) * PB_SZ, r0c, n0, (c + 1) * 64, tid);
            CP_COMMIT();
        }

        uint32_t ah_[4][4], al_[4][4];
        #pragma unroll
        for (int st = 0; st < 4; st++) {
            uint32_t a = cur + sw128(arow * 128 + (uint32_t)(2 * st + aseg) * 16);
            ldsm4(ah_[st][0], ah_[st][1], ah_[st][2], ah_[st][3], a + PB_AH);
            ldsm4(al_[st][0], al_[st][1], al_[st][2], al_[st][3], a + PB_AL);
        }
        #pragma unroll
        for (int st = 0; st < 4; st++) {
            #pragma unroll
            for (int g = 0; g < 4; g++) {
                uint32_t off = sw128((uint32_t)((16 * g + krow) * 128 + (2 * st + kseg) * 16));
                uint32_t b0, b1, b2, b3;
                ldsm4(b0, b1, b2, b3, cur + PB_W + off);
                mmafp(acc[2 * g], ah_[st], b0, b1);
                mmafp(acc[2 * g + 1], ah_[st], b2, b3);
                mmafp(acc[2 * g], al_[st], b0, b1);
                mmafp(acc[2 * g + 1], al_[st], b2, b3);
            }
        }
        __syncthreads();
    }

    // epilogue: +bias, relu
    int row0 = r0c + 16 * w + (l >> 2);
    #pragma unroll
    for (int nf = 0; nf < 8; nf++) {
        int col = n0 + 8 * nf + 2 * (l & 3);
        float bx = bias[col], by = bias[col + 1];
        float2 t0 = make_float2(fmaxf(acc[nf][0] + bx, 0.f), fmaxf(acc[nf][1] + by, 0.f));
        float2 t1 = make_float2(fmaxf(acc[nf][2] + bx, 0.f), fmaxf(acc[nf][3] + by, 0.f));
        *(float2*)(out + (size_t)row0 * HID + col) = t0;
        *(float2*)(out + (size_t)(row0 + 8) * HID + col) = t1;
    }
}

// ---------------- launch ----------------
extern "C" void kernel_launch(void* const* d_in, const int* in_sizes, int n_in,
                              void* d_out, int out_size)
{
    const float* q    = (const float*)d_in[0];
    const float* ek   = (const float*)d_in[1];
    const float* ev   = (const float*)d_in[2];
    const float* mask = (const float*)d_in[3];
    const float* wo_w = (const float*)d_in[4];
    const float* wo_b = (const float*)d_in[5];
    float* out = (float*)d_out;

    cudaFuncSetAttribute(attn_tc, cudaFuncAttributeMaxDynamicSharedMemorySize, ATT_SMEM);
    cudaFuncSetAttribute(proj_tc, cudaFuncAttributeMaxDynamicSharedMemorySize, PROJ_SMEM);

    zero_flag_k<<<1, 1>>>();
    scan_mask_k<<<1024, 256>>>(mask, NB * T2 * T2 / 4);

    dim3 gS((NB * T1 * HID / 2) / 256, 3);
    split3_k<<<gS, 256>>>(q, ek, ev);
    convw_k<<<(HID * HID / 2) / 256, 256>>>(wo_w);

    dim3 gA(T1 / 128, BH);
    attn_tc<<<gA, 256, ATT_SMEM>>>(mask);

    dim3 gP(NB * T1 / 128, HID / 64);
    proj_tc<<<gP, 256, PROJ_SMEM>>>(wo_b, out);
}

// round 8
// speedup vs baseline: 5.3423x; 1.3276x over previous
#include <cuda_runtime.h>
#include <cuda_bf16.h>
#include <cuda_fp16.h>
#include <cstdint>

#define HEADS 16
#define DH    64
#define NB    2
#define T1    2048
#define T2    2048
#define HID   1024
#define BH    (NB*HEADS)

// ---------------- device scratch ----------------
__device__ __nv_bfloat16 g_qhi[(size_t)NB * T1 * HID];
__device__ __nv_bfloat16 g_qlo[(size_t)NB * T1 * HID];
__device__ __nv_bfloat16 g_khi[(size_t)NB * T2 * HID];
__device__ __nv_bfloat16 g_klo[(size_t)NB * T2 * HID];
__device__ __half        g_vf [(size_t)NB * T2 * HID];   // V, single fp16
__device__ __half        g_wf [(size_t)HID * HID];       // W, single fp16
__device__ __half        g_ch [(size_t)NB * T1 * HID];   // ctx, single fp16
__device__ int g_mask_flag;

// ---------------- helpers ----------------
__device__ __forceinline__ uint32_t smem_u32(const void* p) {
    uint32_t a;
    asm("{ .reg .u64 t; cvta.to.shared.u64 t, %1; cvt.u32.u64 %0, t; }" : "=r"(a) : "l"(p));
    return a;
}
__device__ __forceinline__ uint32_t sw128(uint32_t o) { return o ^ ((o >> 3) & 0x70); }

__device__ __forceinline__ float bf16r(float x) { return __bfloat162float(__float2bfloat16(x)); }
__device__ __forceinline__ uint32_t packbf2(float lo, float hi) {
    uint32_t r;
    asm("cvt.rn.bf16x2.f32 %0, %1, %2;" : "=r"(r) : "f"(hi), "f"(lo));
    return r;
}
__device__ __forceinline__ uint32_t packh2(float x, float y) {
    __half2 H = __floats2half2_rn(x, y);
    return *(uint32_t*)&H;
}

__device__ __forceinline__ void ldsm4(uint32_t& r0, uint32_t& r1, uint32_t& r2, uint32_t& r3, uint32_t a) {
    asm volatile("ldmatrix.sync.aligned.m8n8.x4.shared.b16 {%0,%1,%2,%3}, [%4];"
        : "=r"(r0), "=r"(r1), "=r"(r2), "=r"(r3) : "r"(a));
}
__device__ __forceinline__ void ldsm4t(uint32_t& r0, uint32_t& r1, uint32_t& r2, uint32_t& r3, uint32_t a) {
    asm volatile("ldmatrix.sync.aligned.m8n8.x4.trans.shared.b16 {%0,%1,%2,%3}, [%4];"
        : "=r"(r0), "=r"(r1), "=r"(r2), "=r"(r3) : "r"(a));
}
__device__ __forceinline__ void mmabf(float* c, const uint32_t* a, uint32_t b0, uint32_t b1) {
    asm volatile("mma.sync.aligned.m16n8k16.row.col.f32.bf16.bf16.f32 "
        "{%0,%1,%2,%3}, {%4,%5,%6,%7}, {%8,%9}, {%0,%1,%2,%3};"
        : "+f"(c[0]), "+f"(c[1]), "+f"(c[2]), "+f"(c[3])
        : "r"(a[0]), "r"(a[1]), "r"(a[2]), "r"(a[3]), "r"(b0), "r"(b1));
}
__device__ __forceinline__ void mmafp(float* c, const uint32_t* a, uint32_t b0, uint32_t b1) {
    asm volatile("mma.sync.aligned.m16n8k16.row.col.f32.f16.f16.f32 "
        "{%0,%1,%2,%3}, {%4,%5,%6,%7}, {%8,%9}, {%0,%1,%2,%3};"
        : "+f"(c[0]), "+f"(c[1]), "+f"(c[2]), "+f"(c[3])
        : "r"(a[0]), "r"(a[1]), "r"(a[2]), "r"(a[3]), "r"(b0), "r"(b1));
}

#define CP16(dst, src) asm volatile("cp.async.cg.shared.global [%0], [%1], 16;" :: "r"(dst), "l"(src) : "memory")
#define CP_COMMIT()    asm volatile("cp.async.commit_group;" ::: "memory")
#define CP_WAIT1()     asm volatile("cp.async.wait_group 1;" ::: "memory")
#define CP_WAIT0()     asm volatile("cp.async.wait_group 0;" ::: "memory")

// ---------------- mask scan ----------------
__global__ void zero_flag_k() { g_mask_flag = 0; }
__global__ void scan_mask_k(const float* __restrict__ m, int n4) {
    int i = blockIdx.x * blockDim.x + threadIdx.x;
    bool nz = false;
    for (int idx = i; idx < n4; idx += gridDim.x * blockDim.x) {
        float4 v = ((const float4*)m)[idx];
        nz |= (v.x != 0.f) || (v.y != 0.f) || (v.z != 0.f) || (v.w != 0.f);
    }
    if (nz) atomicOr(&g_mask_flag, 1);
}

// ---------------- prep: q,k -> bf16 hi/lo ; v -> fp16 ----------------
__global__ __launch_bounds__(256) void split3_k(const float* __restrict__ q,
                                                const float* __restrict__ k,
                                                const float* __restrict__ v) {
    size_t i = (size_t)blockIdx.x * 256 + threadIdx.x;
    int which = blockIdx.y;
    if (which == 2) {
        float2 u = ((const float2*)v)[i];
        ((__half2*)g_vf)[i] = __floats2half2_rn(u.x, u.y);
        return;
    }
    const float* src = which == 0 ? q : k;
    __nv_bfloat16* hi = which == 0 ? g_qhi : g_khi;
    __nv_bfloat16* lo = which == 0 ? g_qlo : g_klo;
    float2 u = ((const float2*)src)[i];
    float h0 = bf16r(u.x), h1 = bf16r(u.y);
    ((uint32_t*)hi)[i] = packbf2(h0, h1);
    ((uint32_t*)lo)[i] = packbf2(u.x - h0, u.y - h1);
}
__global__ __launch_bounds__(256) void convw_k(const float* __restrict__ w) {
    size_t i = (size_t)blockIdx.x * 256 + threadIdx.x;
    float2 u = ((const float2*)w)[i];
    ((__half2*)g_wf)[i] = __floats2half2_rn(u.x, u.y);
}

// ---------------- attention (FA2; S = bf16x3, PV = fp16x1) ----------------
// smem buffer: KH | KL | VF, 8KB each (64 rows x 128B, sw128); 3 buffers
#define AT_BUF   24576
#define AO_KH    0
#define AO_KL    8192
#define AO_VF    16384
#define ATT_SMEM (3 * AT_BUF + 1024)

__device__ __forceinline__ void issue_tile(uint32_t sbuf, int k0, int tid,
    const __nv_bfloat16* khg, const __nv_bfloat16* klg, const __half* vfg)
{
    #pragma unroll
    for (int j = 0; j < 2; j++) {
        int i = tid * 2 + j;
        int row = i >> 3, seg = i & 7;
        uint32_t dsw = sw128((uint32_t)(row * 128 + seg * 16));
        size_t roff = (size_t)(k0 + row) * HID + seg * 8;
        CP16(sbuf + AO_KH + dsw, khg + roff);
        CP16(sbuf + AO_KL + dsw, klg + roff);
        CP16(sbuf + AO_VF + dsw, vfg + roff);
    }
}

__global__ __launch_bounds__(256, 2) void attn_tc(const float* __restrict__ mask)
{
    extern __shared__ char smraw[];
    uint32_t sb0 = smem_u32(smraw);
    uint32_t pad = (1024u - (sb0 & 1023u)) & 1023u;
    char* smp = smraw + pad;
    uint32_t sb = sb0 + pad;

    const int tid = threadIdx.x;
    const int w = tid >> 5, l = tid & 31;
    const int bh = blockIdx.y, b = bh >> 4, h = bh & 15;
    const int q0 = blockIdx.x * 128;

    const __nv_bfloat16* khg = g_khi + (size_t)b * T2 * HID + h * DH;
    const __nv_bfloat16* klg = g_klo + (size_t)b * T2 * HID + h * DH;
    const __half*        vfg = g_vf  + (size_t)b * T2 * HID + h * DH;

    // ---- load Q fragments (persist in registers), staged through buf0 ----
    uint32_t qh_[4][4], ql_[4][4];
    {
        const __nv_bfloat16* qhg = g_qhi + ((size_t)b * T1 + q0) * HID + h * DH;
        const __nv_bfloat16* qlg = g_qlo + ((size_t)b * T1 + q0) * HID + h * DH;
        const uint32_t qrow = (uint32_t)(16 * w + (l & 15));
        #pragma unroll
        for (int pass = 0; pass < 2; pass++) {
            const __nv_bfloat16* src = pass ? qlg : qhg;
            #pragma unroll
            for (int j = 0; j < 4; j++) {
                int i = tid * 4 + j;
                int row = i >> 3, seg = i & 7;
                *(uint4*)(smp + sw128((uint32_t)(row * 128 + seg * 16))) =
                    *(const uint4*)(src + (size_t)row * HID + seg * 8);
            }
            __syncthreads();
            #pragma unroll
            for (int st = 0; st < 4; st++) {
                uint32_t a = sb + sw128(qrow * 128 + (uint32_t)(2 * st + (l >> 4)) * 16);
                if (pass == 0) ldsm4(qh_[st][0], qh_[st][1], qh_[st][2], qh_[st][3], a);
                else           ldsm4(ql_[st][0], ql_[st][1], ql_[st][2], ql_[st][3], a);
            }
            __syncthreads();
        }
    }

    // kick off tiles 0,1 into bufs 0,1
    issue_tile(sb, 0, tid, khg, klg, vfg);
    CP_COMMIT();
    issue_tile(sb + AT_BUF, 64, tid, khg, klg, vfg);
    CP_COMMIT();

    const bool use_mask = (g_mask_flag != 0);
    const float* mr0 = mask + ((size_t)b * T2 + (q0 + 16 * w + (l >> 2))) * T2;
    const float* mr1 = mr0 + (size_t)8 * T2;

    const uint32_t krow = (uint32_t)((l & 7) + ((l & 16) >> 1)); // + 16*g
    const uint32_t kseg = (uint32_t)((l >> 3) & 1);              // + 2*st
    const uint32_t vrow = (uint32_t)((l & 7) + (l & 8));         // + 16*st
    const uint32_t vseg = (uint32_t)(l >> 4);                    // + 2*g

    float o_[8][4];
    #pragma unroll
    for (int i = 0; i < 8; i++)
        #pragma unroll
        for (int j = 0; j < 4; j++) o_[i][j] = 0.f;
    float m0 = -1e30f, m1 = -1e30f, l0 = 0.f, l1 = 0.f;

    int ci = 0, ii = 2;
    for (int kt = 0; kt < 32; kt++) {
        if (kt == 31) { CP_WAIT0(); } else { CP_WAIT1(); }
        __syncthreads();
        if (kt + 2 < 32) {
            issue_tile(sb + (uint32_t)ii * AT_BUF, (kt + 2) * 64, tid, khg, klg, vfg);
            CP_COMMIT();
        }
        uint32_t cur = sb + (uint32_t)ci * AT_BUF;
        ci = (ci == 2) ? 0 : ci + 1;
        ii = (ii == 2) ? 0 : ii + 1;

        // ---- S = Qhi*Khi + Qhi*Klo + Qlo*Khi (bf16 x3) ----
        float s_[8][4];
        #pragma unroll
        for (int i = 0; i < 8; i++)
            #pragma unroll
            for (int j = 0; j < 4; j++) s_[i][j] = 0.f;

        #pragma unroll
        for (int st = 0; st < 4; st++) {
            #pragma unroll
            for (int g = 0; g < 4; g++) {
                uint32_t off = sw128((uint32_t)((16 * g + krow) * 128 + (2 * st + kseg) * 16));
                uint32_t b0, b1, b2, b3;
                ldsm4(b0, b1, b2, b3, cur + AO_KH + off);
                mmabf(s_[2 * g], qh_[st], b0, b1);
                mmabf(s_[2 * g + 1], qh_[st], b2, b3);
                mmabf(s_[2 * g], ql_[st], b0, b1);
                mmabf(s_[2 * g + 1], ql_[st], b2, b3);
                uint32_t c0, c1, c2, c3;
                ldsm4(c0, c1, c2, c3, cur + AO_KL + off);
                mmabf(s_[2 * g], qh_[st], c0, c1);
                mmabf(s_[2 * g + 1], qh_[st], c2, c3);
            }
        }

        if (use_mask) {
            int k0 = kt * 64;
            #pragma unroll
            for (int nf = 0; nf < 8; nf++) {
                float2 a = *(const float2*)(mr0 + k0 + 8 * nf + 2 * (l & 3));
                float2 c = *(const float2*)(mr1 + k0 + 8 * nf + 2 * (l & 3));
                s_[nf][0] += a.x; s_[nf][1] += a.y;
                s_[nf][2] += c.x; s_[nf][3] += c.y;
            }
        }

        // ---- online softmax ----
        float mt0 = -1e30f, mt1 = -1e30f;
        #pragma unroll
        for (int nf = 0; nf < 8; nf++) {
            mt0 = fmaxf(mt0, fmaxf(s_[nf][0], s_[nf][1]));
            mt1 = fmaxf(mt1, fmaxf(s_[nf][2], s_[nf][3]));
        }
        mt0 = fmaxf(mt0, __shfl_xor_sync(0xffffffffu, mt0, 1));
        mt0 = fmaxf(mt0, __shfl_xor_sync(0xffffffffu, mt0, 2));
        mt1 = fmaxf(mt1, __shfl_xor_sync(0xffffffffu, mt1, 1));
        mt1 = fmaxf(mt1, __shfl_xor_sync(0xffffffffu, mt1, 2));
        float nm0 = fmaxf(m0, mt0), nm1 = fmaxf(m1, mt1);
        float cr0 = __expf(m0 - nm0), cr1 = __expf(m1 - nm1);
        m0 = nm0; m1 = nm1;
        float sum0 = 0.f, sum1 = 0.f;
        #pragma unroll
        for (int nf = 0; nf < 8; nf++) {
            s_[nf][0] = __expf(s_[nf][0] - nm0); sum0 += s_[nf][0];
            s_[nf][1] = __expf(s_[nf][1] - nm0); sum0 += s_[nf][1];
            s_[nf][2] = __expf(s_[nf][2] - nm1); sum1 += s_[nf][2];
            s_[nf][3] = __expf(s_[nf][3] - nm1); sum1 += s_[nf][3];
        }
        sum0 += __shfl_xor_sync(0xffffffffu, sum0, 1);
        sum0 += __shfl_xor_sync(0xffffffffu, sum0, 2);
        sum1 += __shfl_xor_sync(0xffffffffu, sum1, 1);
        sum1 += __shfl_xor_sync(0xffffffffu, sum1, 2);
        l0 = l0 * cr0 + sum0;
        l1 = l1 * cr1 + sum1;
        #pragma unroll
        for (int nf = 0; nf < 8; nf++) {
            o_[nf][0] *= cr0; o_[nf][1] *= cr0;
            o_[nf][2] *= cr1; o_[nf][3] *= cr1;
        }

        // ---- pack P -> fp16 A fragments (single precision plane) ----
        uint32_t ph_[4][4];
        #pragma unroll
        for (int st = 0; st < 4; st++) {
            ph_[st][0] = packh2(s_[2 * st][0],     s_[2 * st][1]);
            ph_[st][1] = packh2(s_[2 * st][2],     s_[2 * st][3]);
            ph_[st][2] = packh2(s_[2 * st + 1][0], s_[2 * st + 1][1]);
            ph_[st][3] = packh2(s_[2 * st + 1][2], s_[2 * st + 1][3]);
        }

        // ---- O += P*V (fp16 x1) ----
        #pragma unroll
        for (int st = 0; st < 4; st++) {
            #pragma unroll
            for (int g = 0; g < 4; g++) {
                uint32_t off = sw128((uint32_t)((16 * st + vrow) * 128 + (2 * g + vseg) * 16));
                uint32_t b0, b1, b2, b3;
                ldsm4t(b0, b1, b2, b3, cur + AO_VF + off);
                mmafp(o_[2 * g], ph_[st], b0, b1);
                mmafp(o_[2 * g + 1], ph_[st], b2, b3);
            }
        }
    }

    // ---- epilogue: normalize, write fp16 ctx ----
    float inv0 = 1.0f / l0, inv1 = 1.0f / l1;
    int r0 = q0 + 16 * w + (l >> 2);
    size_t base0 = ((size_t)b * T1 + r0) * HID + h * DH;
    size_t base1 = base0 + (size_t)8 * HID;
    #pragma unroll
    for (int nf = 0; nf < 8; nf++) {
        int col = 8 * nf + 2 * (l & 3);
        *(uint32_t*)(g_ch + base0 + col) = packh2(o_[nf][0] * inv0, o_[nf][1] * inv0);
        *(uint32_t*)(g_ch + base1 + col) = packh2(o_[nf][2] * inv1, o_[nf][3] * inv1);
    }
}

// ---------------- proj: out = relu(ctx @ W^T + b), fp16 x1, double-buffered ----------------
#define PB_A  0
#define PB_W  16384
#define PB_SZ 24576
#define PROJ_SMEM (2 * PB_SZ + 1024)

__device__ __forceinline__ void proj_issue(uint32_t sbuf, int r0c, int n0, int e0, int tid)
{
    #pragma unroll
    for (int j = 0; j < 4; j++) {
        int i = tid * 4 + j;
        int row = i >> 3, seg = i & 7;
        uint32_t dsw = sw128((uint32_t)(row * 128 + seg * 16));
        size_t roff = (size_t)(r0c + row) * HID + e0 + seg * 8;
        CP16(sbuf + PB_A + dsw, g_ch + roff);
    }
    #pragma unroll
    for (int j = 0; j < 2; j++) {
        int i = tid * 2 + j;
        int row = i >> 3, seg = i & 7;
        uint32_t dsw = sw128((uint32_t)(row * 128 + seg * 16));
        size_t roff = (size_t)(n0 + row) * HID + e0 + seg * 8;
        CP16(sbuf + PB_W + dsw, g_wf + roff);
    }
}

__global__ __launch_bounds__(256, 2) void proj_tc(const float* __restrict__ bias,
                                                  float* __restrict__ out)
{
    extern __shared__ char smraw[];
    uint32_t sb0 = smem_u32(smraw);
    uint32_t pad = (1024u - (sb0 & 1023u)) & 1023u;
    uint32_t sb = sb0 + pad;

    const int tid = threadIdx.x;
    const int w = tid >> 5, l = tid & 31;
    const int r0c = blockIdx.x * 128, n0 = blockIdx.y * 64;

    const uint32_t arow = (uint32_t)(16 * w + (l & 15));
    const uint32_t aseg = (uint32_t)(l >> 4);
    const uint32_t krow = (uint32_t)((l & 7) + ((l & 16) >> 1));
    const uint32_t kseg = (uint32_t)((l >> 3) & 1);

    float acc[8][4];
    #pragma unroll
    for (int i = 0; i < 8; i++)
        #pragma unroll
        for (int j = 0; j < 4; j++) acc[i][j] = 0.f;

    proj_issue(sb, r0c, n0, 0, tid);
    CP_COMMIT();

    for (int c = 0; c < 16; c++) {
        CP_WAIT0();
        __syncthreads();
        uint32_t cur = sb + (uint32_t)(c & 1) * PB_SZ;
        if (c + 1 < 16) {
            proj_issue(sb + (uint32_t)((c + 1) & 1) * PB_SZ, r0c, n0, (c + 1) * 64, tid);
            CP_COMMIT();
        }

        uint32_t a_[4][4];
        #pragma unroll
        for (int st = 0; st < 4; st++) {
            uint32_t a = cur + PB_A + sw128(arow * 128 + (uint32_t)(2 * st + aseg) * 16);
            ldsm4(a_[st][0], a_[st][1], a_[st][2], a_[st][3], a);
        }
        #pragma unroll
        for (int st = 0; st < 4; st++) {
            #pragma unroll
            for (int g = 0; g < 4; g++) {
                uint32_t off = sw128((uint32_t)((16 * g + krow) * 128 + (2 * st + kseg) * 16));
                uint32_t b0, b1, b2, b3;
                ldsm4(b0, b1, b2, b3, cur + PB_W + off);
                mmafp(acc[2 * g], a_[st], b0, b1);
                mmafp(acc[2 * g + 1], a_[st], b2, b3);
            }
        }
        __syncthreads();
    }

    // epilogue: +bias, relu
    int row0 = r0c + 16 * w + (l >> 2);
    #pragma unroll
    for (int nf = 0; nf < 8; nf++) {
        int col = n0 + 8 * nf + 2 * (l & 3);
        float bx = bias[col], by = bias[col + 1];
        float2 t0 = make_float2(fmaxf(acc[nf][0] + bx, 0.f), fmaxf(acc[nf][1] + by, 0.f));
        float2 t1 = make_float2(fmaxf(acc[nf][2] + bx, 0.f), fmaxf(acc[nf][3] + by, 0.f));
        *(float2*)(out + (size_t)row0 * HID + col) = t0;
        *(float2*)(out + (size_t)(row0 + 8) * HID + col) = t1;
    }
}

// ---------------- launch ----------------
extern "C" void kernel_launch(void* const* d_in, const int* in_sizes, int n_in,
                              void* d_out, int out_size)
{
    const float* q    = (const float*)d_in[0];
    const float* ek   = (const float*)d_in[1];
    const float* ev   = (const float*)d_in[2];
    const float* mask = (const float*)d_in[3];
    const float* wo_w = (const float*)d_in[4];
    const float* wo_b = (const float*)d_in[5];
    float* out = (float*)d_out;

    cudaFuncSetAttribute(attn_tc, cudaFuncAttributeMaxDynamicSharedMemorySize, ATT_SMEM);
    cudaFuncSetAttribute(proj_tc, cudaFuncAttributeMaxDynamicSharedMemorySize, PROJ_SMEM);

    zero_flag_k<<<1, 1>>>();
    scan_mask_k<<<1024, 256>>>(mask, NB * T2 * T2 / 4);

    dim3 gS((NB * T1 * HID / 2) / 256, 3);
    split3_k<<<gS, 256>>>(q, ek, ev);
    convw_k<<<(HID * HID / 2) / 256, 256>>>(wo_w);

    dim3 gA(T1 / 128, BH);
    attn_tc<<<gA, 256, ATT_SMEM>>>(mask);

    dim3 gP(NB * T1 / 128, HID / 64);
    proj_tc<<<gP, 256, PROJ_SMEM>>>(wo_b, out);
}

// round 10
// speedup vs baseline: 5.5389x; 1.0368x over previous
#include <cuda_runtime.h>
#include <cuda_bf16.h>
#include <cuda_fp16.h>
#include <cstdint>

#define HEADS 16
#define DH    64
#define NB    2
#define T1    2048
#define T2    2048
#define HID   1024
#define BH    (NB*HEADS)

// ---------------- device scratch ----------------
__device__ __nv_bfloat16 g_qhi[(size_t)NB * T1 * HID];
__device__ __nv_bfloat16 g_qlo[(size_t)NB * T1 * HID];
__device__ __nv_bfloat16 g_khi[(size_t)NB * T2 * HID];
__device__ __nv_bfloat16 g_klo[(size_t)NB * T2 * HID];
__device__ __half        g_vf [(size_t)NB * T2 * HID];   // V, single fp16
__device__ __half        g_wf [(size_t)HID * HID];       // W, single fp16
__device__ __half        g_ch [(size_t)NB * T1 * HID];   // ctx, single fp16
__device__ int g_mask_flag;

// ---------------- helpers ----------------
__device__ __forceinline__ uint32_t smem_u32(const void* p) {
    uint32_t a;
    asm("{ .reg .u64 t; cvta.to.shared.u64 t, %1; cvt.u32.u64 %0, t; }" : "=r"(a) : "l"(p));
    return a;
}
__device__ __forceinline__ uint32_t sw128(uint32_t o) { return o ^ ((o >> 3) & 0x70); }

__device__ __forceinline__ float bf16r(float x) { return __bfloat162float(__float2bfloat16(x)); }
__device__ __forceinline__ uint32_t packbf2(float lo, float hi) {
    uint32_t r;
    asm("cvt.rn.bf16x2.f32 %0, %1, %2;" : "=r"(r) : "f"(hi), "f"(lo));
    return r;
}
__device__ __forceinline__ uint32_t packh2(float x, float y) {
    __half2 H = __floats2half2_rn(x, y);
    return *(uint32_t*)&H;
}

__device__ __forceinline__ void ldsm4(uint32_t& r0, uint32_t& r1, uint32_t& r2, uint32_t& r3, uint32_t a) {
    asm volatile("ldmatrix.sync.aligned.m8n8.x4.shared.b16 {%0,%1,%2,%3}, [%4];"
        : "=r"(r0), "=r"(r1), "=r"(r2), "=r"(r3) : "r"(a));
}
__device__ __forceinline__ void ldsm4t(uint32_t& r0, uint32_t& r1, uint32_t& r2, uint32_t& r3, uint32_t a) {
    asm volatile("ldmatrix.sync.aligned.m8n8.x4.trans.shared.b16 {%0,%1,%2,%3}, [%4];"
        : "=r"(r0), "=r"(r1), "=r"(r2), "=r"(r3) : "r"(a));
}
__device__ __forceinline__ void mmabf(float* c, const uint32_t* a, uint32_t b0, uint32_t b1) {
    asm volatile("mma.sync.aligned.m16n8k16.row.col.f32.bf16.bf16.f32 "
        "{%0,%1,%2,%3}, {%4,%5,%6,%7}, {%8,%9}, {%0,%1,%2,%3};"
        : "+f"(c[0]), "+f"(c[1]), "+f"(c[2]), "+f"(c[3])
        : "r"(a[0]), "r"(a[1]), "r"(a[2]), "r"(a[3]), "r"(b0), "r"(b1));
}
__device__ __forceinline__ void mmafp(float* c, const uint32_t* a, uint32_t b0, uint32_t b1) {
    asm volatile("mma.sync.aligned.m16n8k16.row.col.f32.f16.f16.f32 "
        "{%0,%1,%2,%3}, {%4,%5,%6,%7}, {%8,%9}, {%0,%1,%2,%3};"
        : "+f"(c[0]), "+f"(c[1]), "+f"(c[2]), "+f"(c[3])
        : "r"(a[0]), "r"(a[1]), "r"(a[2]), "r"(a[3]), "r"(b0), "r"(b1));
}

#define CP16(dst, src) asm volatile("cp.async.cg.shared.global [%0], [%1], 16;" :: "r"(dst), "l"(src) : "memory")
#define CP_COMMIT()    asm volatile("cp.async.commit_group;" ::: "memory")
#define CP_WAIT1()     asm volatile("cp.async.wait_group 1;" ::: "memory")
#define CP_WAIT0()     asm volatile("cp.async.wait_group 0;" ::: "memory")

// ---------------- fused prep: mask scan + q/k split + v/w convert ----------------
__global__ void zero_flag_k() { g_mask_flag = 0; }

__global__ __launch_bounds__(256) void prep_k(const float* __restrict__ q,
                                              const float* __restrict__ k,
                                              const float* __restrict__ v,
                                              const float* __restrict__ w,
                                              const float* __restrict__ mask)
{
    const int job = blockIdx.y;
    const int tid = blockIdx.x * 256 + threadIdx.x;
    const int nth = gridDim.x * 256;

    if (job == 0) {
        // mask nonzero scan (float4 granularity), <=1 atomic per block
        const float4* m4 = (const float4*)mask;
        const int n4 = NB * T2 * T2 / 4;
        bool nz = false;
        for (int i = tid; i < n4; i += nth) {
            float4 u = m4[i];
            nz |= (u.x != 0.f) || (u.y != 0.f) || (u.z != 0.f) || (u.w != 0.f);
        }
        if (__syncthreads_or(nz) && threadIdx.x == 0) atomicOr(&g_mask_flag, 1);
    } else if (job <= 2) {
        const float4* src = (const float4*)(job == 1 ? q : k);
        uint2* hi = (uint2*)(job == 1 ? g_qhi : g_khi);
        uint2* lo = (uint2*)(job == 1 ? g_qlo : g_klo);
        const int n4 = NB * T1 * HID / 4;
        for (int i = tid; i < n4; i += nth) {
            float4 u = src[i];
            float h0 = bf16r(u.x), h1 = bf16r(u.y), h2 = bf16r(u.z), h3 = bf16r(u.w);
            hi[i] = make_uint2(packbf2(h0, h1), packbf2(h2, h3));
            lo[i] = make_uint2(packbf2(u.x - h0, u.y - h1), packbf2(u.z - h2, u.w - h3));
        }
    } else if (job == 3) {
        const float4* src = (const float4*)v;
        uint2* dst = (uint2*)g_vf;
        const int n4 = NB * T2 * HID / 4;
        for (int i = tid; i < n4; i += nth) {
            float4 u = src[i];
            dst[i] = make_uint2(packh2(u.x, u.y), packh2(u.z, u.w));
        }
    } else {
        const float4* src = (const float4*)w;
        uint2* dst = (uint2*)g_wf;
        const int n4 = HID * HID / 4;
        for (int i = tid; i < n4; i += nth) {
            float4 u = src[i];
            dst[i] = make_uint2(packh2(u.x, u.y), packh2(u.z, u.w));
        }
    }
}

// ---------------- attention (FA2; S = bf16x3, PV = fp16x1) ----------------
// smem buffer: KH | KL | VF, 8KB each (64 rows x 128B, sw128); 3 buffers
#define AT_BUF   24576
#define AO_KH    0
#define AO_KL    8192
#define AO_VF    16384
#define ATT_SMEM (3 * AT_BUF + 1024)

__device__ __forceinline__ void issue_tile(uint32_t sbuf, int k0, int tid,
    const __nv_bfloat16* khg, const __nv_bfloat16* klg, const __half* vfg)
{
    #pragma unroll
    for (int j = 0; j < 2; j++) {
        int i = tid * 2 + j;
        int row = i >> 3, seg = i & 7;
        uint32_t dsw = sw128((uint32_t)(row * 128 + seg * 16));
        size_t roff = (size_t)(k0 + row) * HID + seg * 8;
        CP16(sbuf + AO_KH + dsw, khg + roff);
        CP16(sbuf + AO_KL + dsw, klg + roff);
        CP16(sbuf + AO_VF + dsw, vfg + roff);
    }
}

__global__ __launch_bounds__(256, 2) void attn_tc(const float* __restrict__ mask)
{
    extern __shared__ char smraw[];
    uint32_t sb0 = smem_u32(smraw);
    uint32_t pad = (1024u - (sb0 & 1023u)) & 1023u;
    char* smp = smraw + pad;
    uint32_t sb = sb0 + pad;

    const int tid = threadIdx.x;
    const int w = tid >> 5, l = tid & 31;
    const int bh = blockIdx.y, b = bh >> 4, h = bh & 15;
    const int q0 = blockIdx.x * 128;
    const float L2E = 1.4426950408889634f;

    const __nv_bfloat16* khg = g_khi + (size_t)b * T2 * HID + h * DH;
    const __nv_bfloat16* klg = g_klo + (size_t)b * T2 * HID + h * DH;
    const __half*        vfg = g_vf  + (size_t)b * T2 * HID + h * DH;

    // ---- load Q fragments (persist in registers), staged through buf0 ----
    uint32_t qh_[4][4], ql_[4][4];
    {
        const __nv_bfloat16* qhg = g_qhi + ((size_t)b * T1 + q0) * HID + h * DH;
        const __nv_bfloat16* qlg = g_qlo + ((size_t)b * T1 + q0) * HID + h * DH;
        const uint32_t qrow = (uint32_t)(16 * w + (l & 15));
        #pragma unroll
        for (int pass = 0; pass < 2; pass++) {
            const __nv_bfloat16* src = pass ? qlg : qhg;
            #pragma unroll
            for (int j = 0; j < 4; j++) {
                int i = tid * 4 + j;
                int row = i >> 3, seg = i & 7;
                *(uint4*)(smp + sw128((uint32_t)(row * 128 + seg * 16))) =
                    *(const uint4*)(src + (size_t)row * HID + seg * 8);
            }
            __syncthreads();
            #pragma unroll
            for (int st = 0; st < 4; st++) {
                uint32_t a = sb + sw128(qrow * 128 + (uint32_t)(2 * st + (l >> 4)) * 16);
                if (pass == 0) ldsm4(qh_[st][0], qh_[st][1], qh_[st][2], qh_[st][3], a);
                else           ldsm4(ql_[st][0], ql_[st][1], ql_[st][2], ql_[st][3], a);
            }
            __syncthreads();
        }
    }

    // kick off tiles 0,1 into bufs 0,1
    issue_tile(sb, 0, tid, khg, klg, vfg);
    CP_COMMIT();
    issue_tile(sb + AT_BUF, 64, tid, khg, klg, vfg);
    CP_COMMIT();

    const bool use_mask = (g_mask_flag != 0);
    const float* mr0 = mask + ((size_t)b * T2 + (q0 + 16 * w + (l >> 2))) * T2;
    const float* mr1 = mr0 + (size_t)8 * T2;

    const uint32_t krow = (uint32_t)((l & 7) + ((l & 16) >> 1)); // + 16*g
    const uint32_t kseg = (uint32_t)((l >> 3) & 1);              // + 2*st
    const uint32_t vrow = (uint32_t)((l & 7) + (l & 8));         // + 16*st
    const uint32_t vseg = (uint32_t)(l >> 4);                    // + 2*g

    float o_[8][4];
    #pragma unroll
    for (int i = 0; i < 8; i++)
        #pragma unroll
        for (int j = 0; j < 4; j++) o_[i][j] = 0.f;
    float m0 = -1e30f, m1 = -1e30f, l0 = 0.f, l1 = 0.f;

    int ci = 0, ii = 2;
    for (int kt = 0; kt < 32; kt++) {
        if (kt == 31) { CP_WAIT0(); } else { CP_WAIT1(); }
        __syncthreads();
        if (kt + 2 < 32) {
            issue_tile(sb + (uint32_t)ii * AT_BUF, (kt + 2) * 64, tid, khg, klg, vfg);
            CP_COMMIT();
        }
        uint32_t cur = sb + (uint32_t)ci * AT_BUF;
        ci = (ci == 2) ? 0 : ci + 1;
        ii = (ii == 2) ? 0 : ii + 1;

        // ---- S = Qhi*Khi + Qhi*Klo + Qlo*Khi (bf16 x3) ----
        float s_[8][4];
        #pragma unroll
        for (int i = 0; i < 8; i++)
            #pragma unroll
            for (int j = 0; j < 4; j++) s_[i][j] = 0.f;

        #pragma unroll
        for (int st = 0; st < 4; st++) {
            #pragma unroll
            for (int g = 0; g < 4; g++) {
                uint32_t off = sw128((uint32_t)((16 * g + krow) * 128 + (2 * st + kseg) * 16));
                uint32_t b0, b1, b2, b3;
                ldsm4(b0, b1, b2, b3, cur + AO_KH + off);
                mmabf(s_[2 * g], qh_[st], b0, b1);
                mmabf(s_[2 * g + 1], qh_[st], b2, b3);
                mmabf(s_[2 * g], ql_[st], b0, b1);
                mmabf(s_[2 * g + 1], ql_[st], b2, b3);
                uint32_t c0, c1, c2, c3;
                ldsm4(c0, c1, c2, c3, cur + AO_KL + off);
                mmabf(s_[2 * g], qh_[st], c0, c1);
                mmabf(s_[2 * g + 1], qh_[st], c2, c3);
            }
        }

        if (use_mask) {
            int k0 = kt * 64;
            #pragma unroll
            for (int nf = 0; nf < 8; nf++) {
                float2 a = *(const float2*)(mr0 + k0 + 8 * nf + 2 * (l & 3));
                float2 c = *(const float2*)(mr1 + k0 + 8 * nf + 2 * (l & 3));
                s_[nf][0] += a.x; s_[nf][1] += a.y;
                s_[nf][2] += c.x; s_[nf][3] += c.y;
            }
        }

        // ---- online softmax: tree max ----
        float a0 = fmaxf(s_[0][0], s_[0][1]), a1 = fmaxf(s_[1][0], s_[1][1]);
        float a2 = fmaxf(s_[2][0], s_[2][1]), a3 = fmaxf(s_[3][0], s_[3][1]);
        float a4 = fmaxf(s_[4][0], s_[4][1]), a5 = fmaxf(s_[5][0], s_[5][1]);
        float a6 = fmaxf(s_[6][0], s_[6][1]), a7 = fmaxf(s_[7][0], s_[7][1]);
        float mt0 = fmaxf(fmaxf(fmaxf(a0, a1), fmaxf(a2, a3)),
                          fmaxf(fmaxf(a4, a5), fmaxf(a6, a7)));
        float b0_ = fmaxf(s_[0][2], s_[0][3]), b1_ = fmaxf(s_[1][2], s_[1][3]);
        float b2_ = fmaxf(s_[2][2], s_[2][3]), b3_ = fmaxf(s_[3][2], s_[3][3]);
        float b4_ = fmaxf(s_[4][2], s_[4][3]), b5_ = fmaxf(s_[5][2], s_[5][3]);
        float b6_ = fmaxf(s_[6][2], s_[6][3]), b7_ = fmaxf(s_[7][2], s_[7][3]);
        float mt1 = fmaxf(fmaxf(fmaxf(b0_, b1_), fmaxf(b2_, b3_)),
                          fmaxf(fmaxf(b4_, b5_), fmaxf(b6_, b7_)));
        mt0 = fmaxf(mt0, __shfl_xor_sync(0xffffffffu, mt0, 1));
        mt0 = fmaxf(mt0, __shfl_xor_sync(0xffffffffu, mt0, 2));
        mt1 = fmaxf(mt1, __shfl_xor_sync(0xffffffffu, mt1, 1));
        mt1 = fmaxf(mt1, __shfl_xor_sync(0xffffffffu, mt1, 2));
        float nm0 = fmaxf(m0, mt0), nm1 = fmaxf(m1, mt1);
        float cr0 = exp2f((m0 - nm0) * L2E);
        float cr1 = exp2f((m1 - nm1) * L2E);
        m0 = nm0; m1 = nm1;
        float nmL0 = nm0 * L2E, nmL1 = nm1 * L2E;

        // o-rescale first (independent FMULs interleave with the MUFU burst below)
        #pragma unroll
        for (int nf = 0; nf < 8; nf++) {
            o_[nf][0] *= cr0; o_[nf][1] *= cr0;
            o_[nf][2] *= cr1; o_[nf][3] *= cr1;
        }

        // exp via single FFMA + MUFU each
        #pragma unroll
        for (int nf = 0; nf < 8; nf++) {
            s_[nf][0] = exp2f(fmaf(s_[nf][0], L2E, -nmL0));
            s_[nf][1] = exp2f(fmaf(s_[nf][1], L2E, -nmL0));
            s_[nf][2] = exp2f(fmaf(s_[nf][2], L2E, -nmL1));
            s_[nf][3] = exp2f(fmaf(s_[nf][3], L2E, -nmL1));
        }

        // tree sums
        float u0 = (s_[0][0] + s_[0][1]) + (s_[1][0] + s_[1][1]);
        float u1 = (s_[2][0] + s_[2][1]) + (s_[3][0] + s_[3][1]);
        float u2 = (s_[4][0] + s_[4][1]) + (s_[5][0] + s_[5][1]);
        float u3 = (s_[6][0] + s_[6][1]) + (s_[7][0] + s_[7][1]);
        float sum0 = (u0 + u1) + (u2 + u3);
        float w0 = (s_[0][2] + s_[0][3]) + (s_[1][2] + s_[1][3]);
        float w1 = (s_[2][2] + s_[2][3]) + (s_[3][2] + s_[3][3]);
        float w2 = (s_[4][2] + s_[4][3]) + (s_[5][2] + s_[5][3]);
        float w3 = (s_[6][2] + s_[6][3]) + (s_[7][2] + s_[7][3]);
        float sum1 = (w0 + w1) + (w2 + w3);
        sum0 += __shfl_xor_sync(0xffffffffu, sum0, 1);
        sum0 += __shfl_xor_sync(0xffffffffu, sum0, 2);
        sum1 += __shfl_xor_sync(0xffffffffu, sum1, 1);
        sum1 += __shfl_xor_sync(0xffffffffu, sum1, 2);
        l0 = l0 * cr0 + sum0;
        l1 = l1 * cr1 + sum1;

        // ---- pack P -> fp16 A fragments ----
        uint32_t ph_[4][4];
        #pragma unroll
        for (int st = 0; st < 4; st++) {
            ph_[st][0] = packh2(s_[2 * st][0],     s_[2 * st][1]);
            ph_[st][1] = packh2(s_[2 * st][2],     s_[2 * st][3]);
            ph_[st][2] = packh2(s_[2 * st + 1][0], s_[2 * st + 1][1]);
            ph_[st][3] = packh2(s_[2 * st + 1][2], s_[2 * st + 1][3]);
        }

        // ---- O += P*V (fp16 x1) ----
        #pragma unroll
        for (int st = 0; st < 4; st++) {
            #pragma unroll
            for (int g = 0; g < 4; g++) {
                uint32_t off = sw128((uint32_t)((16 * st + vrow) * 128 + (2 * g + vseg) * 16));
                uint32_t b0, b1, b2, b3;
                ldsm4t(b0, b1, b2, b3, cur + AO_VF + off);
                mmafp(o_[2 * g], ph_[st], b0, b1);
                mmafp(o_[2 * g + 1], ph_[st], b2, b3);
            }
        }
    }

    // ---- epilogue: normalize, write fp16 ctx ----
    float inv0 = 1.0f / l0, inv1 = 1.0f / l1;
    int r0 = q0 + 16 * w + (l >> 2);
    size_t base0 = ((size_t)b * T1 + r0) * HID + h * DH;
    size_t base1 = base0 + (size_t)8 * HID;
    #pragma unroll
    for (int nf = 0; nf < 8; nf++) {
        int col = 8 * nf + 2 * (l & 3);
        *(uint32_t*)(g_ch + base0 + col) = packh2(o_[nf][0] * inv0, o_[nf][1] * inv0);
        *(uint32_t*)(g_ch + base1 + col) = packh2(o_[nf][2] * inv1, o_[nf][3] * inv1);
    }
}

// ---------------- proj: out = relu(ctx @ W^T + b), fp16 x1, double-buffered ----------------
#define PB_A  0
#define PB_W  16384
#define PB_SZ 24576
#define PROJ_SMEM (2 * PB_SZ + 1024)

__device__ __forceinline__ void proj_issue(uint32_t sbuf, int r0c, int n0, int e0, int tid)
{
    #pragma unroll
    for (int j = 0; j < 4; j++) {
        int i = tid * 4 + j;
        int row = i >> 3, seg = i & 7;
        uint32_t dsw = sw128((uint32_t)(row * 128 + seg * 16));
        size_t roff = (size_t)(r0c + row) * HID + e0 + seg * 8;
        CP16(sbuf + PB_A + dsw, g_ch + roff);
    }
    #pragma unroll
    for (int j = 0; j < 2; j++) {
        int i = tid * 2 + j;
        int row = i >> 3, seg = i & 7;
        uint32_t dsw = sw128((uint32_t)(row * 128 + seg * 16));
        size_t roff = (size_t)(n0 + row) * HID + e0 + seg * 8;
        CP16(sbuf + PB_W + dsw, g_wf + roff);
    }
}

__global__ __launch_bounds__(256, 2) void proj_tc(const float* __restrict__ bias,
                                                  float* __restrict__ out)
{
    extern __shared__ char smraw[];
    uint32_t sb0 = smem_u32(smraw);
    uint32_t pad = (1024u - (sb0 & 1023u)) & 1023u;
    uint32_t sb = sb0 + pad;

    const int tid = threadIdx.x;
    const int w = tid >> 5, l = tid & 31;
    const int r0c = blockIdx.x * 128, n0 = blockIdx.y * 64;

    const uint32_t arow = (uint32_t)(16 * w + (l & 15));
    const uint32_t aseg = (uint32_t)(l >> 4);
    const uint32_t krow = (uint32_t)((l & 7) + ((l & 16) >> 1));
    const uint32_t kseg = (uint32_t)((l >> 3) & 1);

    float acc[8][4];
    #pragma unroll
    for (int i = 0; i < 8; i++)
        #pragma unroll
        for (int j = 0; j < 4; j++) acc[i][j] = 0.f;

    proj_issue(sb, r0c, n0, 0, tid);
    CP_COMMIT();

    for (int c = 0; c < 16; c++) {
        CP_WAIT0();
        __syncthreads();
        uint32_t cur = sb + (uint32_t)(c & 1) * PB_SZ;
        if (c + 1 < 16) {
            proj_issue(sb + (uint32_t)((c + 1) & 1) * PB_SZ, r0c, n0, (c + 1) * 64, tid);
            CP_COMMIT();
        }

        uint32_t a_[4][4];
        #pragma unroll
        for (int st = 0; st < 4; st++) {
            uint32_t a = cur + PB_A + sw128(arow * 128 + (uint32_t)(2 * st + aseg) * 16);
            ldsm4(a_[st][0], a_[st][1], a_[st][2], a_[st][3], a);
        }
        #pragma unroll
        for (int st = 0; st < 4; st++) {
            #pragma unroll
            for (int g = 0; g < 4; g++) {
                uint32_t off = sw128((uint32_t)((16 * g + krow) * 128 + (2 * st + kseg) * 16));
                uint32_t b0, b1, b2, b3;
                ldsm4(b0, b1, b2, b3, cur + PB_W + off);
                mmafp(acc[2 * g], a_[st], b0, b1);
                mmafp(acc[2 * g + 1], a_[st], b2, b3);
            }
        }
        __syncthreads();
    }

    // epilogue: +bias, relu
    int row0 = r0c + 16 * w + (l >> 2);
    #pragma unroll
    for (int nf = 0; nf < 8; nf++) {
        int col = n0 + 8 * nf + 2 * (l & 3);
        float bx = bias[col], by = bias[col + 1];
        float2 t0 = make_float2(fmaxf(acc[nf][0] + bx, 0.f), fmaxf(acc[nf][1] + by, 0.f));
        float2 t1 = make_float2(fmaxf(acc[nf][2] + bx, 0.f), fmaxf(acc[nf][3] + by, 0.f));
        *(float2*)(out + (size_t)row0 * HID + col) = t0;
        *(float2*)(out + (size_t)(row0 + 8) * HID + col) = t1;
    }
}

// ---------------- launch ----------------
extern "C" void kernel_launch(void* const* d_in, const int* in_sizes, int n_in,
                              void* d_out, int out_size)
{
    const float* q    = (const float*)d_in[0];
    const float* ek   = (const float*)d_in[1];
    const float* ev   = (const float*)d_in[2];
    const float* mask = (const float*)d_in[3];
    const float* wo_w = (const float*)d_in[4];
    const float* wo_b = (const float*)d_in[5];
    float* out = (float*)d_out;

    cudaFuncSetAttribute(attn_tc, cudaFuncAttributeMaxDynamicSharedMemorySize, ATT_SMEM);
    cudaFuncSetAttribute(proj_tc, cudaFuncAttributeMaxDynamicSharedMemorySize, PROJ_SMEM);

    zero_flag_k<<<1, 1>>>();

    dim3 gPr(512, 5);
    prep_k<<<gPr, 256>>>(q, ek, ev, wo_w, mask);

    dim3 gA(T1 / 128, BH);
    attn_tc<<<gA, 256, ATT_SMEM>>>(mask);

    dim3 gP(NB * T1 / 128, HID / 64);
    proj_tc<<<gP, 256, PROJ_SMEM>>>(wo_b, out);
}